// round 11
// baseline (speedup 1.0000x reference)
#include <cuda_runtime.h>
#include <cuda_bf16.h>
#include <math.h>
#include <stdint.h>

#define Nn 50000
#define Ee 800000
#define HID 64
#define EAD 16
#define NLAY 3
#define NCLS 10
#define NGR 64
#define KTOT 576
#define MTILES ((Nn + 127)/128)
#define SCB ((Nn + 255)/256)          // 196 scan blocks

// ---------------- static scratch ----------------
__device__ float d_x[(size_t)Nn*HID];
__device__ int   d_srcs[Ee];
__device__ int   d_eperm[Ee];
__device__ int   d_degi[Nn];
__device__ int   d_off[Nn+1];
__device__ int   d_cursor[Nn];
__device__ int   d_bsum[SCB];
__device__ int   d_boff[SCB];
__device__ float d_amp[Nn], d_att[Nn];
__device__ float d_avglog;
__device__ __align__(16) __nv_bfloat16 d_aggH[(size_t)Nn*KTOT];
__device__ __align__(16) __nv_bfloat16 d_aggL[(size_t)Nn*KTOT];
__device__ __align__(16) __nv_bfloat16 d_BH[(size_t)192*KTOT];
__device__ __align__(16) __nv_bfloat16 d_BL[(size_t)192*KTOT];
__device__ float d_cvec[192];
__device__ float d_y[(size_t)Nn*192];
__device__ float d_h[(size_t)Nn*HID];
__device__ float d_bnsum[NLAY*HID], d_bnss[NLAY*HID];
__device__ float d_pool[NGR*HID];
__device__ float d_cntg[NGR];

// ---------------- setup kernels ----------------
__global__ __launch_bounds__(256) void k_zero() {
    int i = blockIdx.x*blockDim.x + threadIdx.x;
    if (i < Nn) { d_degi[i] = 0; d_cursor[i] = 0; }
    if (i < NGR*HID) d_pool[i] = 0.f;
    if (i < NGR) d_cntg[i] = 0.f;
    if (i < NLAY*HID) { d_bnsum[i] = 0.f; d_bnss[i] = 0.f; }
    if (i == 0) { d_avglog = 0.f; d_off[Nn] = Ee; }
}

__global__ __launch_bounds__(256) void k_node_enc(const float* __restrict__ x,
                           const float* __restrict__ w, const float* __restrict__ b) {
    __shared__ float Ws[64*64];
    __shared__ float xs[4][64];
    int t = threadIdx.x;
    for (int i = t; i < 4096; i += 256) Ws[i] = w[i];
    int r = t >> 6, c = t & 63;
    int n = blockIdx.x*4 + r;
    if (n < Nn) xs[r][c] = x[(size_t)n*64 + c];
    __syncthreads();
    if (n < Nn) {
        float s = b[c];
        #pragma unroll
        for (int k = 0; k < 64; k++) s += xs[r][k]*Ws[k*64 + c];
        d_x[(size_t)n*64 + c] = s;
    }
}

__global__ __launch_bounds__(256) void k_deg(const int* __restrict__ dst) {
    int e = blockIdx.x*blockDim.x + threadIdx.x;
    if (e < Ee) atomicAdd(&d_degi[dst[e]], 1);
}

// scan pass 1: per-block degree sums + avg-log reduction
__global__ __launch_bounds__(256) void k_scan1() {
    __shared__ int si[256];
    __shared__ float sl[256];
    int t = threadIdx.x;
    int i = blockIdx.x*256 + t;
    int d = (i < Nn) ? d_degi[i] : 0;
    si[t] = d;
    sl[t] = (i < Nn) ? logf((float)d + 1.f) : 0.f;
    __syncthreads();
    for (int o = 128; o > 0; o >>= 1) {
        if (t < o) { si[t] += si[t+o]; sl[t] += sl[t+o]; }
        __syncthreads();
    }
    if (t == 0) {
        d_bsum[blockIdx.x] = si[0];
        atomicAdd(&d_avglog, sl[0]);
    }
}

// scan pass 2: exclusive scan of SCB block sums (1 block)
__global__ __launch_bounds__(256) void k_scan2() {
    __shared__ int sm[256];
    int t = threadIdx.x;
    int v = (t < SCB) ? d_bsum[t] : 0;
    sm[t] = v; __syncthreads();
    for (int o = 1; o < 256; o <<= 1) {
        int u = (t >= o) ? sm[t-o] : 0;
        __syncthreads();
        sm[t] += u;
        __syncthreads();
    }
    if (t < SCB) d_boff[t] = sm[t] - v;
}

// scan pass 3: local exclusive scan + block offset
__global__ __launch_bounds__(256) void k_scan3() {
    __shared__ int sm[256];
    int t = threadIdx.x;
    int i = blockIdx.x*256 + t;
    int d = (i < Nn) ? d_degi[i] : 0;
    sm[t] = d; __syncthreads();
    for (int o = 1; o < 256; o <<= 1) {
        int u = (t >= o) ? sm[t-o] : 0;
        __syncthreads();
        sm[t] += u;
        __syncthreads();
    }
    if (i < Nn) d_off[i] = sm[t] - d + d_boff[blockIdx.x];
}

__global__ __launch_bounds__(256) void k_sort(const int* __restrict__ src,
                                              const int* __restrict__ dst) {
    int e = blockIdx.x*blockDim.x + threadIdx.x;
    if (e < Ee) {
        int d = dst[e];
        int r = atomicAdd(&d_cursor[d], 1);
        int pos = d_off[d] + r;
        d_srcs[pos]  = src[e];
        d_eperm[pos] = e;
    }
}

__global__ __launch_bounds__(256) void k_amp() {
    int n = blockIdx.x*blockDim.x + threadIdx.x;
    if (n < Nn) {
        float degc = fmaxf((float)d_degi[n], 1.f);
        float ld = logf(degc + 1.f);
        float avg = d_avglog / (float)Nn;
        d_amp[n] = ld/avg;
        d_att[n] = avg/ld;
    }
}

// ---------------- aggregation ----------------
__device__ __forceinline__ void sthl(size_t idx, float v) {
    __nv_bfloat16 h = __float2bfloat16(v);
    d_aggH[idx] = h;
    d_aggL[idx] = __float2bfloat16(v - __bfloat162float(h));
}

// ONCE: fused edge-attr encode + dst-segment stats -> ea columns of d_agg
// 4 nodes per block, 64 threads per node (thread = output dim)
__global__ __launch_bounds__(256) void k_ea_agg(const float* __restrict__ eattr,
                         const float* __restrict__ w, const float* __restrict__ b) {
    __shared__ float Ws[16*64];
    __shared__ float Bs[64];
    int t = threadIdx.x;
    for (int i = t; i < 1024; i += 256) Ws[i] = w[i];
    if (t < 64) Bs[t] = b[t];
    __syncthreads();
    int sub = t >> 6, c = t & 63;
    int n = blockIdx.x*4 + sub;
    if (n >= Nn) return;
    int e0 = d_off[n], e1 = d_off[n+1];
    float s = 0.f, ss = 0.f, mx = -3.4e38f, mn = 3.4e38f;
    for (int p = e0; p < e1; p++) {
        int e = d_eperm[p];
        const float4* pr = (const float4*)(eattr + (size_t)e*EAD);
        float4 r0 = pr[0], r1 = pr[1], r2 = pr[2], r3 = pr[3];
        float v = Bs[c];
        v += r0.x*Ws[c]       + r0.y*Ws[64+c]  + r0.z*Ws[128+c] + r0.w*Ws[192+c];
        v += r1.x*Ws[256+c]   + r1.y*Ws[320+c] + r1.z*Ws[384+c] + r1.w*Ws[448+c];
        v += r2.x*Ws[512+c]   + r2.y*Ws[576+c] + r2.z*Ws[640+c] + r2.w*Ws[704+c];
        v += r3.x*Ws[768+c]   + r3.y*Ws[832+c] + r3.z*Ws[896+c] + r3.w*Ws[960+c];
        s += v; ss += v*v;
        mx = fmaxf(mx, v); mn = fminf(mn, v);
    }
    int deg = e1 - e0;
    float inv = 1.f / fmaxf((float)deg, 1.f);
    float mean = s*inv;
    float sd   = sqrtf(fmaxf(ss*inv - mean*mean, 0.f) + 1e-5f);
    if (deg == 0) { mx = 0.f; mn = 0.f; }
    size_t base = (size_t)n*KTOT + 64 + c;
    sthl(base,       mean);
    sthl(base + 128, mn);
    sthl(base + 256, mx);
    sthl(base + 384, sd);
}

// PER LAYER: x-src side stats + masked x. 4 nodes/block, no smem, x4 unrolled.
__global__ __launch_bounds__(256) void k_xagg() {
    int t = threadIdx.x;
    int sub = t >> 6, c = t & 63;
    int n = blockIdx.x*4 + sub;
    if (n >= Nn) return;
    int e0 = d_off[n], e1 = d_off[n+1];
    float s = 0.f, ss = 0.f, mx = -3.4e38f, mn = 3.4e38f;
    int p = e0;
    for (; p + 4 <= e1; p += 4) {
        int s0 = d_srcs[p], s1 = d_srcs[p+1], s2 = d_srcs[p+2], s3 = d_srcs[p+3];
        float v0 = d_x[(size_t)s0*64 + c];
        float v1 = d_x[(size_t)s1*64 + c];
        float v2 = d_x[(size_t)s2*64 + c];
        float v3 = d_x[(size_t)s3*64 + c];
        s  += (v0 + v1) + (v2 + v3);
        ss += (v0*v0 + v1*v1) + (v2*v2 + v3*v3);
        mx = fmaxf(fmaxf(mx, v0), fmaxf(v1, fmaxf(v2, v3)));
        mn = fminf(fminf(mn, v0), fminf(v1, fminf(v2, v3)));
    }
    for (; p < e1; p++) {
        float v = d_x[(size_t)d_srcs[p]*64 + c];
        s += v; ss += v*v;
        mx = fmaxf(mx, v); mn = fminf(mn, v);
    }
    int deg = e1 - e0;
    float inv = 1.f / fmaxf((float)deg, 1.f);
    float mean = s*inv;
    float sd   = sqrtf(fmaxf(ss*inv - mean*mean, 0.f) + 1e-5f);
    if (deg == 0) { mx = 0.f; mn = 0.f; }
    size_t b = (size_t)n*KTOT + c;
    sthl(b,       mean);
    sthl(b + 128, mn);
    sthl(b + 256, mx);
    sthl(b + 384, sd);
    float m2 = (deg > 0) ? d_x[(size_t)n*64 + c] : 0.f;
    sthl((size_t)n*KTOT + 512 + c, m2);
}

// folded B [192 x 576] bf16 hi/lo (row = output col; layout Bt[n][k]) + cvec
__global__ __launch_bounds__(64) void k_prepB(const float* __restrict__ convw, int l) {
    int c = blockIdx.x;             // 0..191 output column
    int tch = c >> 6, cc = c & 63;
    const float* W = convw + ((size_t)l*2304 + (size_t)tch*768)*64;
    const int LUT[8] = {64,128,256,320,448,512,640,704};
    for (int k = threadIdx.x; k < KTOT; k += 64) {
        float v;
        if (k < 512) {
            v = W[(size_t)(LUT[k >> 6] + (k & 63))*64 + cc];
        } else {
            int r = k - 512;
            v = W[(size_t)r*64 + cc] + W[(size_t)(192 + r)*64 + cc] + W[(size_t)(384 + r)*64 + cc];
        }
        __nv_bfloat16 h = __float2bfloat16(v);
        d_BH[(size_t)c*KTOT + k] = h;
        d_BL[(size_t)c*KTOT + k] = __float2bfloat16(v - __bfloat162float(h));
    }
    if (threadIdx.x == 0) {
        float s = 0.f;
        for (int r = 0; r < 64; r++) s += W[(size_t)(576 + r)*64 + cc];
        d_cvec[c] = 0.0031622776601683794f * s;   // sqrt(1e-5) * sum(W_std_dst)
    }
}

// ------------- warp-mma bf16 GEMM: d_y[128 tile, 192] += A@B (3 hi/lo combos) -------------
#define ASTR 40                       // smem row stride in halves (conflict-free)
#define SMA_HALVES (128*ASTR)         // 5120
#define SMB_HALVES (192*ASTR)         // 7680
#define BUF_HALVES (SMA_HALVES + SMB_HALVES)   // 12800
#define SMEM_GEMM (2*BUF_HALVES*2)    // bytes = 51200

__global__ __launch_bounds__(256) void k_gemm_mma() {
    extern __shared__ __nv_bfloat16 smg[];
    int t = threadIdx.x;
    int lane = t & 31, warp = t >> 5;
    int warpM = warp & 3, warpN = warp >> 2;     // 4 x 2 warp grid
    int bm = blockIdx.x * 128;
    int g = lane >> 2, tg = lane & 3;

    float c[2][12][4];
    #pragma unroll
    for (int m = 0; m < 2; m++)
        #pragma unroll
        for (int j = 0; j < 12; j++)
            #pragma unroll
            for (int q = 0; q < 4; q++) c[m][j][q] = 0.f;

    int arow = t >> 1, akoff = (t & 1) * 16;     // A: 128 rows x 32 halves
    uint4 ra0, ra1, rb0, rb1, rb2;

    const int NIT = 54;                          // 3 combos x 18 chunks
    {
        const __nv_bfloat16* As = d_aggH;
        const __nv_bfloat16* Bs = d_BH;
        int grow = bm + arow;
        if (grow < Nn) {
            const __nv_bfloat16* p = As + (size_t)grow*KTOT + akoff;
            ra0 = *(const uint4*)p; ra1 = *(const uint4*)(p + 8);
        } else { ra0 = make_uint4(0,0,0,0); ra1 = ra0; }
        int u0 = t, u1 = t + 256, u2 = t + 512;
        rb0 = *(const uint4*)(Bs + (size_t)(u0>>2)*KTOT + (u0&3)*8);
        rb1 = *(const uint4*)(Bs + (size_t)(u1>>2)*KTOT + (u1&3)*8);
        rb2 = *(const uint4*)(Bs + (size_t)(u2>>2)*KTOT + (u2&3)*8);
    }

    for (int it = 0; it < NIT; it++) {
        __nv_bfloat16* buf  = smg + (it & 1)*BUF_HALVES;
        __nv_bfloat16* abuf = buf;
        __nv_bfloat16* bbuf = buf + SMA_HALVES;
        *(uint4*)(abuf + arow*ASTR + akoff)     = ra0;
        *(uint4*)(abuf + arow*ASTR + akoff + 8) = ra1;
        {
            int u0 = t, u1 = t + 256, u2 = t + 512;
            *(uint4*)(bbuf + (u0>>2)*ASTR + (u0&3)*8) = rb0;
            *(uint4*)(bbuf + (u1>>2)*ASTR + (u1&3)*8) = rb1;
            *(uint4*)(bbuf + (u2>>2)*ASTR + (u2&3)*8) = rb2;
        }
        __syncthreads();
        if (it + 1 < NIT) {
            int nit = it + 1;
            int combo = nit / 18, kc = nit % 18, k0 = kc * 32;
            const __nv_bfloat16* As = (combo == 2) ? d_aggL : d_aggH;
            const __nv_bfloat16* Bs = (combo == 1) ? d_BL   : d_BH;
            int grow = bm + arow;
            if (grow < Nn) {
                const __nv_bfloat16* p = As + (size_t)grow*KTOT + k0 + akoff;
                ra0 = *(const uint4*)p; ra1 = *(const uint4*)(p + 8);
            } else { ra0 = make_uint4(0,0,0,0); ra1 = ra0; }
            int u0 = t, u1 = t + 256, u2 = t + 512;
            rb0 = *(const uint4*)(Bs + (size_t)(u0>>2)*KTOT + k0 + (u0&3)*8);
            rb1 = *(const uint4*)(Bs + (size_t)(u1>>2)*KTOT + k0 + (u1&3)*8);
            rb2 = *(const uint4*)(Bs + (size_t)(u2>>2)*KTOT + k0 + (u2&3)*8);
        }
        #pragma unroll
        for (int ks = 0; ks < 2; ks++) {
            uint32_t a[2][4];
            #pragma unroll
            for (int m = 0; m < 2; m++) {
                int r0 = warpM*32 + m*16;
                const __nv_bfloat16* p0 = abuf + (r0 + g)*ASTR + ks*16 + tg*2;
                const __nv_bfloat16* p1 = abuf + (r0 + g + 8)*ASTR + ks*16 + tg*2;
                a[m][0] = *(const uint32_t*)p0;
                a[m][1] = *(const uint32_t*)p1;
                a[m][2] = *(const uint32_t*)(p0 + 8);
                a[m][3] = *(const uint32_t*)(p1 + 8);
            }
            #pragma unroll
            for (int j = 0; j < 12; j++) {
                int n0 = warpN*96 + j*8 + g;
                const __nv_bfloat16* pb = bbuf + n0*ASTR + ks*16 + tg*2;
                uint32_t b0 = *(const uint32_t*)pb;
                uint32_t b1 = *(const uint32_t*)(pb + 8);
                #pragma unroll
                for (int m = 0; m < 2; m++) {
                    asm volatile(
                        "mma.sync.aligned.m16n8k16.row.col.f32.bf16.bf16.f32 "
                        "{%0,%1,%2,%3}, {%4,%5,%6,%7}, {%8,%9}, {%0,%1,%2,%3};"
                        : "+f"(c[m][j][0]), "+f"(c[m][j][1]),
                          "+f"(c[m][j][2]), "+f"(c[m][j][3])
                        : "r"(a[m][0]), "r"(a[m][1]), "r"(a[m][2]), "r"(a[m][3]),
                          "r"(b0), "r"(b1));
                }
            }
        }
        __syncthreads();
    }

    #pragma unroll
    for (int m = 0; m < 2; m++) {
        int r0 = bm + warpM*32 + m*16 + g;
        #pragma unroll
        for (int j = 0; j < 12; j++) {
            int col = warpN*96 + j*8 + tg*2;
            if (r0 < Nn) {
                d_y[(size_t)r0*192 + col]     = c[m][j][0];
                d_y[(size_t)r0*192 + col + 1] = c[m][j][1];
            }
            if (r0 + 8 < Nn) {
                d_y[(size_t)(r0+8)*192 + col]     = c[m][j][2];
                d_y[(size_t)(r0+8)*192 + col + 1] = c[m][j][3];
            }
        }
    }
}

// fused combine (cvec/amp/att/bias) + BN statistics accumulation
__global__ __launch_bounds__(256) void k_combine_bn(const float* __restrict__ convb, int l) {
    __shared__ float sm1[256], sm2[256];
    int t = threadIdx.x;
    int col = t & 63, rg = t >> 6;
    float cv0 = d_cvec[col], cv1 = d_cvec[64 + col], cv2 = d_cvec[128 + col];
    float bias = convb[l*64 + col];
    float s = 0.f, ss = 0.f;
    for (int r = blockIdx.x*4 + rg; r < Nn; r += gridDim.x*4) {
        size_t b = (size_t)r*192;
        float y0 = d_y[b + col]       + cv0;
        float y1 = d_y[b + 64 + col]  + cv1;
        float y2 = d_y[b + 128 + col] + cv2;
        float h = y0 + d_amp[r]*y1 + d_att[r]*y2 + bias;
        d_h[(size_t)r*64 + col] = h;
        s += h; ss += h*h;
    }
    sm1[t] = s; sm2[t] = ss; __syncthreads();
    if (t < 64) {
        float a = sm1[t] + sm1[t+64] + sm1[t+128] + sm1[t+192];
        float c = sm2[t] + sm2[t+64] + sm2[t+128] + sm2[t+192];
        atomicAdd(&d_bnsum[l*64 + t], a);
        atomicAdd(&d_bnss[l*64 + t], c);
    }
}

__global__ __launch_bounds__(256) void k_bnapply(const float* __restrict__ g,
                                                 const float* __restrict__ b, int l) {
    int i = blockIdx.x*blockDim.x + threadIdx.x;
    if (i >= Nn*64) return;
    int j = i & 63;
    float mu  = d_bnsum[l*64 + j] / (float)Nn;
    float var = d_bnss[l*64 + j] / (float)Nn - mu*mu;
    float h = (d_h[i] - mu) * rsqrtf(var + 1e-5f) * g[l*64 + j] + b[l*64 + j];
    d_x[i] = fmaxf(h, 0.f) + d_x[i];
}

// ---------------- readout ----------------
__global__ __launch_bounds__(256) void k_pool(const int* __restrict__ batch) {
    int i = blockIdx.x*blockDim.x + threadIdx.x;
    if (i >= Nn*64) return;
    int n = i >> 6, j = i & 63;
    int bg = batch[n];
    atomicAdd(&d_pool[bg*64 + j], d_x[i]);
    if (j == 0) atomicAdd(&d_cntg[bg], 1.f);
}

__global__ __launch_bounds__(256) void k_final(const float* __restrict__ f1w,
                        const float* __restrict__ f1b,
                        const float* __restrict__ f2w, const float* __restrict__ f2b,
                        const float* __restrict__ f3w, const float* __restrict__ f3b,
                        float* __restrict__ out) {
    __shared__ float G[64*64], H1[64*32], H2[64*16];
    int t = threadIdx.x;
    for (int i = t; i < 4096; i += 256) {
        int g = i >> 6;
        G[i] = d_pool[i] / fmaxf(d_cntg[g], 1.f);
    }
    __syncthreads();
    for (int i = t; i < 2048; i += 256) {
        int g = i >> 5, o = i & 31;
        float s = f1b[o];
        #pragma unroll
        for (int k = 0; k < 64; k++) s += G[g*64 + k]*f1w[k*32 + o];
        H1[i] = fmaxf(s, 0.f);
    }
    __syncthreads();
    for (int i = t; i < 1024; i += 256) {
        int g = i >> 4, o = i & 15;
        float s = f2b[o];
        #pragma unroll
        for (int k = 0; k < 32; k++) s += H1[g*32 + k]*f2w[k*16 + o];
        H2[i] = fmaxf(s, 0.f);
    }
    __syncthreads();
    for (int i = t; i < 640; i += 256) {
        int g = i/10, o = i%10;
        float s = f3b[o];
        #pragma unroll
        for (int k = 0; k < 16; k++) s += H2[g*16 + k]*f3w[k*10 + o];
        out[i] = s;
    }
}

// ---------------- launch ----------------
extern "C" void kernel_launch(void* const* d_in, const int* in_sizes, int n_in,
                              void* d_out, int out_size) {
    const float* x      = (const float*)d_in[0];
    const int*   ei     = (const int*)  d_in[1];
    const int*   batch  = (const int*)  d_in[2];
    const float* eattr  = (const float*)d_in[3];
    const float* node_w = (const float*)d_in[4];
    const float* node_b = (const float*)d_in[5];
    const float* edge_w = (const float*)d_in[6];
    const float* edge_b = (const float*)d_in[7];
    const float* conv_w = (const float*)d_in[8];
    const float* conv_b = (const float*)d_in[9];
    const float* bn_g   = (const float*)d_in[10];
    const float* bn_b   = (const float*)d_in[11];
    const float* f1w    = (const float*)d_in[12];
    const float* f1b    = (const float*)d_in[13];
    const float* f2w    = (const float*)d_in[14];
    const float* f2b    = (const float*)d_in[15];
    const float* f3w    = (const float*)d_in[16];
    const float* f3b    = (const float*)d_in[17];
    float* out = (float*)d_out;

    const int* src = ei;
    const int* dst = ei + Ee;

    static int smset = 0;
    if (!smset) {
        cudaFuncSetAttribute(k_gemm_mma, cudaFuncAttributeMaxDynamicSharedMemorySize, SMEM_GEMM);
        smset = 1;
    }

    k_zero<<<(Nn + 255)/256, 256>>>();
    k_node_enc<<<(Nn + 3)/4, 256>>>(x, node_w, node_b);
    k_deg<<<(Ee + 255)/256, 256>>>(dst);
    k_scan1<<<SCB, 256>>>();
    k_scan2<<<1, 256>>>();
    k_scan3<<<SCB, 256>>>();
    k_sort<<<(Ee + 255)/256, 256>>>(src, dst);
    k_ea_agg<<<(Nn + 3)/4, 256>>>(eattr, edge_w, edge_b);
    k_amp<<<(Nn + 255)/256, 256>>>();

    for (int l = 0; l < NLAY; l++) {
        k_xagg<<<(Nn + 3)/4, 256>>>();
        k_prepB<<<192, 64>>>(conv_w, l);
        k_gemm_mma<<<MTILES, 256, SMEM_GEMM>>>();
        k_combine_bn<<<128, 256>>>(conv_b, l);
        k_bnapply<<<(Nn*64 + 255)/256, 256>>>(bn_g, bn_b, l);
    }

    k_pool<<<(Nn*64 + 255)/256, 256>>>(batch);
    k_final<<<1, 256>>>(f1w, f1b, f2w, f2b, f3w, f3b, out);
}

// round 12
// speedup vs baseline: 1.1663x; 1.1663x over previous
#include <cuda_runtime.h>
#include <cuda_bf16.h>
#include <math.h>
#include <stdint.h>

#define Nn 50000
#define Ee 800000
#define HID 64
#define EAD 16
#define NLAY 3
#define NCLS 10
#define NGR 64
#define KTOT 576
#define MTILES ((Nn + 127)/128)
#define SCB ((Nn + 255)/256)          // 196 scan blocks

// ---------------- static scratch ----------------
__device__ float d_x[(size_t)Nn*HID];
__device__ float d_ea[(size_t)Ee*HID];
__device__ int   d_srcs[Ee];
__device__ int   d_eperm[Ee];
__device__ int   d_degi[Nn];
__device__ int   d_off[Nn+1];
__device__ int   d_cursor[Nn];
__device__ int   d_bsum[SCB];
__device__ int   d_boff[SCB];
__device__ float d_amp[Nn], d_att[Nn];
__device__ float d_avglog;
__device__ __align__(16) __nv_bfloat16 d_aggH[(size_t)Nn*KTOT];
__device__ __align__(16) __nv_bfloat16 d_aggL[(size_t)Nn*KTOT];
__device__ __align__(16) __nv_bfloat16 d_BH[(size_t)192*KTOT];
__device__ __align__(16) __nv_bfloat16 d_BL[(size_t)192*KTOT];
__device__ float d_cvec[192];
__device__ float d_y[(size_t)Nn*192];
__device__ float d_h[(size_t)Nn*HID];
__device__ float d_bnsum[NLAY*HID], d_bnss[NLAY*HID];
__device__ float d_pool[NGR*HID];
__device__ float d_cntg[NGR];

// ---------------- setup kernels ----------------
__global__ __launch_bounds__(256) void k_zero() {
    int i = blockIdx.x*blockDim.x + threadIdx.x;
    if (i < Nn) { d_degi[i] = 0; d_cursor[i] = 0; }
    if (i < NGR*HID) d_pool[i] = 0.f;
    if (i < NGR) d_cntg[i] = 0.f;
    if (i < NLAY*HID) { d_bnsum[i] = 0.f; d_bnss[i] = 0.f; }
    if (i == 0) { d_avglog = 0.f; d_off[Nn] = Ee; }
}

__global__ __launch_bounds__(256) void k_node_enc(const float* __restrict__ x,
                           const float* __restrict__ w, const float* __restrict__ b) {
    __shared__ float Ws[64*64];
    __shared__ float xs[4][64];
    int t = threadIdx.x;
    for (int i = t; i < 4096; i += 256) Ws[i] = w[i];
    int r = t >> 6, c = t & 63;
    int n = blockIdx.x*4 + r;
    if (n < Nn) xs[r][c] = x[(size_t)n*64 + c];
    __syncthreads();
    if (n < Nn) {
        float s = b[c];
        #pragma unroll
        for (int k = 0; k < 64; k++) s += xs[r][k]*Ws[k*64 + c];
        d_x[(size_t)n*64 + c] = s;
    }
}

__global__ __launch_bounds__(256) void k_deg(const int* __restrict__ dst) {
    int e = blockIdx.x*blockDim.x + threadIdx.x;
    if (e < Ee) atomicAdd(&d_degi[dst[e]], 1);
}

// scan pass 1: per-block degree sums + avg-log reduction
__global__ __launch_bounds__(256) void k_scan1() {
    __shared__ int si[256];
    __shared__ float sl[256];
    int t = threadIdx.x;
    int i = blockIdx.x*256 + t;
    int d = (i < Nn) ? d_degi[i] : 0;
    si[t] = d;
    sl[t] = (i < Nn) ? logf((float)d + 1.f) : 0.f;
    __syncthreads();
    for (int o = 128; o > 0; o >>= 1) {
        if (t < o) { si[t] += si[t+o]; sl[t] += sl[t+o]; }
        __syncthreads();
    }
    if (t == 0) {
        d_bsum[blockIdx.x] = si[0];
        atomicAdd(&d_avglog, sl[0]);
    }
}

// scan pass 2: exclusive scan of SCB block sums (1 block)
__global__ __launch_bounds__(256) void k_scan2() {
    __shared__ int sm[256];
    int t = threadIdx.x;
    int v = (t < SCB) ? d_bsum[t] : 0;
    sm[t] = v; __syncthreads();
    for (int o = 1; o < 256; o <<= 1) {
        int u = (t >= o) ? sm[t-o] : 0;
        __syncthreads();
        sm[t] += u;
        __syncthreads();
    }
    if (t < SCB) d_boff[t] = sm[t] - v;
}

// scan pass 3: local exclusive scan + block offset
__global__ __launch_bounds__(256) void k_scan3() {
    __shared__ int sm[256];
    int t = threadIdx.x;
    int i = blockIdx.x*256 + t;
    int d = (i < Nn) ? d_degi[i] : 0;
    sm[t] = d; __syncthreads();
    for (int o = 1; o < 256; o <<= 1) {
        int u = (t >= o) ? sm[t-o] : 0;
        __syncthreads();
        sm[t] += u;
        __syncthreads();
    }
    if (i < Nn) d_off[i] = sm[t] - d + d_boff[blockIdx.x];
}

__global__ __launch_bounds__(256) void k_sort(const int* __restrict__ src,
                                              const int* __restrict__ dst) {
    int e = blockIdx.x*blockDim.x + threadIdx.x;
    if (e < Ee) {
        int d = dst[e];
        int r = atomicAdd(&d_cursor[d], 1);
        int pos = d_off[d] + r;
        d_srcs[pos]  = src[e];
        d_eperm[pos] = e;
    }
}

__global__ __launch_bounds__(256) void k_ea_enc(const float* __restrict__ ea,
                         const float* __restrict__ w, const float* __restrict__ b) {
    __shared__ float Ws[16*64];
    __shared__ float es[4][16];
    int t = threadIdx.x;
    for (int i = t; i < 1024; i += 256) Ws[i] = w[i];
    int r = t >> 6, c = t & 63;
    int p = blockIdx.x*4 + r;
    if (p < Ee && c < 16) {
        int e = d_eperm[p];
        es[r][c] = ea[(size_t)e*EAD + c];
    }
    __syncthreads();
    if (p < Ee) {
        float s = b[c];
        #pragma unroll
        for (int k = 0; k < 16; k++) s += es[r][k]*Ws[k*64 + c];
        d_ea[(size_t)p*64 + c] = s;
    }
}

__global__ __launch_bounds__(256) void k_amp() {
    int n = blockIdx.x*blockDim.x + threadIdx.x;
    if (n < Nn) {
        float degc = fmaxf((float)d_degi[n], 1.f);
        float ld = logf(degc + 1.f);
        float avg = d_avglog / (float)Nn;
        d_amp[n] = ld/avg;
        d_att[n] = avg/ld;
    }
}

// ---------------- per-layer kernels ----------------
__device__ __forceinline__ void sthl(size_t idx, float v) {
    __nv_bfloat16 h = __float2bfloat16(v);
    d_aggH[idx] = h;
    d_aggL[idx] = __float2bfloat16(v - __bfloat162float(h));
}

// edge aggregation + fold: A = [mean|mn|mx|std of (src,ea) (512) | masked x (64)]
// 1 node/block, 128 threads; in-place x4 unroll, no smem staging
__global__ __launch_bounds__(128) void k_agg() {
    int n = blockIdx.x;
    int t = threadIdx.x;            // 0..127
    int e0 = d_off[n], e1 = d_off[n+1];
    bool isx = t < 64;
    int c = t & 63;
    float s = 0.f, ss = 0.f, mx = -3.4e38f, mn = 3.4e38f;
    int p = e0;
    for (; p + 4 <= e1; p += 4) {
        float v0, v1, v2, v3;
        if (isx) {
            int s0 = d_srcs[p], s1 = d_srcs[p+1], s2 = d_srcs[p+2], s3 = d_srcs[p+3];
            v0 = d_x[(size_t)s0*64 + c];
            v1 = d_x[(size_t)s1*64 + c];
            v2 = d_x[(size_t)s2*64 + c];
            v3 = d_x[(size_t)s3*64 + c];
        } else {
            const float* pe = d_ea + (size_t)p*64 + c;
            v0 = pe[0]; v1 = pe[64]; v2 = pe[128]; v3 = pe[192];
        }
        s  += (v0 + v1) + (v2 + v3);
        ss += (v0*v0 + v1*v1) + (v2*v2 + v3*v3);
        mx = fmaxf(fmaxf(mx, v0), fmaxf(v1, fmaxf(v2, v3)));
        mn = fminf(fminf(mn, v0), fminf(v1, fminf(v2, v3)));
    }
    for (; p < e1; p++) {
        float v;
        if (isx) v = d_x[(size_t)d_srcs[p]*64 + c];
        else     v = d_ea[(size_t)p*64 + c];
        s += v; ss += v*v;
        mx = fmaxf(mx, v); mn = fminf(mn, v);
    }
    int deg = e1 - e0;
    float inv = 1.f / fmaxf((float)deg, 1.f);
    float mean = s*inv;
    float sd   = sqrtf(fmaxf(ss*inv - mean*mean, 0.f) + 1e-5f);
    if (deg == 0) { mx = 0.f; mn = 0.f; }
    size_t b = (size_t)n*KTOT + t;
    sthl(b,       mean);
    sthl(b + 128, mn);
    sthl(b + 256, mx);
    sthl(b + 384, sd);
    if (isx) {
        float m2 = (deg > 0) ? d_x[(size_t)n*64 + t] : 0.f;
        sthl((size_t)n*KTOT + 512 + t, m2);
    }
}

// folded B [192 x 576] bf16 hi/lo (row = output col; layout Bt[n][k]) + cvec
__global__ __launch_bounds__(64) void k_prepB(const float* __restrict__ convw, int l) {
    int c = blockIdx.x;             // 0..191 output column
    int tch = c >> 6, cc = c & 63;
    const float* W = convw + ((size_t)l*2304 + (size_t)tch*768)*64;
    const int LUT[8] = {64,128,256,320,448,512,640,704};
    for (int k = threadIdx.x; k < KTOT; k += 64) {
        float v;
        if (k < 512) {
            v = W[(size_t)(LUT[k >> 6] + (k & 63))*64 + cc];
        } else {
            int r = k - 512;
            v = W[(size_t)r*64 + cc] + W[(size_t)(192 + r)*64 + cc] + W[(size_t)(384 + r)*64 + cc];
        }
        __nv_bfloat16 h = __float2bfloat16(v);
        d_BH[(size_t)c*KTOT + k] = h;
        d_BL[(size_t)c*KTOT + k] = __float2bfloat16(v - __bfloat162float(h));
    }
    if (threadIdx.x == 0) {
        float s = 0.f;
        for (int r = 0; r < 64; r++) s += W[(size_t)(576 + r)*64 + cc];
        d_cvec[c] = 0.0031622776601683794f * s;   // sqrt(1e-5) * sum(W_std_dst)
    }
}

// ------------- warp-mma bf16 GEMM: d_y[128 tile, 192] += A@B (3 hi/lo combos) -------------
#define ASTR 40                       // smem row stride in halves (conflict-free)
#define SMA_HALVES (128*ASTR)         // 5120
#define SMB_HALVES (192*ASTR)         // 7680
#define BUF_HALVES (SMA_HALVES + SMB_HALVES)   // 12800
#define SMEM_GEMM (2*BUF_HALVES*2)    // bytes = 51200

__global__ __launch_bounds__(256) void k_gemm_mma() {
    extern __shared__ __nv_bfloat16 smg[];
    int t = threadIdx.x;
    int lane = t & 31, warp = t >> 5;
    int warpM = warp & 3, warpN = warp >> 2;     // 4 x 2 warp grid
    int bm = blockIdx.x * 128;
    int g = lane >> 2, tg = lane & 3;

    float c[2][12][4];
    #pragma unroll
    for (int m = 0; m < 2; m++)
        #pragma unroll
        for (int j = 0; j < 12; j++)
            #pragma unroll
            for (int q = 0; q < 4; q++) c[m][j][q] = 0.f;

    int arow = t >> 1, akoff = (t & 1) * 16;     // A: 128 rows x 32 halves
    uint4 ra0, ra1, rb0, rb1, rb2;

    const int NIT = 54;                          // 3 combos x 18 chunks
    {
        const __nv_bfloat16* As = d_aggH;
        const __nv_bfloat16* Bs = d_BH;
        int grow = bm + arow;
        if (grow < Nn) {
            const __nv_bfloat16* p = As + (size_t)grow*KTOT + akoff;
            ra0 = *(const uint4*)p; ra1 = *(const uint4*)(p + 8);
        } else { ra0 = make_uint4(0,0,0,0); ra1 = ra0; }
        int u0 = t, u1 = t + 256, u2 = t + 512;
        rb0 = *(const uint4*)(Bs + (size_t)(u0>>2)*KTOT + (u0&3)*8);
        rb1 = *(const uint4*)(Bs + (size_t)(u1>>2)*KTOT + (u1&3)*8);
        rb2 = *(const uint4*)(Bs + (size_t)(u2>>2)*KTOT + (u2&3)*8);
    }

    for (int it = 0; it < NIT; it++) {
        __nv_bfloat16* buf  = smg + (it & 1)*BUF_HALVES;
        __nv_bfloat16* abuf = buf;
        __nv_bfloat16* bbuf = buf + SMA_HALVES;
        *(uint4*)(abuf + arow*ASTR + akoff)     = ra0;
        *(uint4*)(abuf + arow*ASTR + akoff + 8) = ra1;
        {
            int u0 = t, u1 = t + 256, u2 = t + 512;
            *(uint4*)(bbuf + (u0>>2)*ASTR + (u0&3)*8) = rb0;
            *(uint4*)(bbuf + (u1>>2)*ASTR + (u1&3)*8) = rb1;
            *(uint4*)(bbuf + (u2>>2)*ASTR + (u2&3)*8) = rb2;
        }
        __syncthreads();
        if (it + 1 < NIT) {
            int nit = it + 1;
            int combo = nit / 18, kc = nit % 18, k0 = kc * 32;
            const __nv_bfloat16* As = (combo == 2) ? d_aggL : d_aggH;
            const __nv_bfloat16* Bs = (combo == 1) ? d_BL   : d_BH;
            int grow = bm + arow;
            if (grow < Nn) {
                const __nv_bfloat16* p = As + (size_t)grow*KTOT + k0 + akoff;
                ra0 = *(const uint4*)p; ra1 = *(const uint4*)(p + 8);
            } else { ra0 = make_uint4(0,0,0,0); ra1 = ra0; }
            int u0 = t, u1 = t + 256, u2 = t + 512;
            rb0 = *(const uint4*)(Bs + (size_t)(u0>>2)*KTOT + k0 + (u0&3)*8);
            rb1 = *(const uint4*)(Bs + (size_t)(u1>>2)*KTOT + k0 + (u1&3)*8);
            rb2 = *(const uint4*)(Bs + (size_t)(u2>>2)*KTOT + k0 + (u2&3)*8);
        }
        #pragma unroll
        for (int ks = 0; ks < 2; ks++) {
            uint32_t a[2][4];
            #pragma unroll
            for (int m = 0; m < 2; m++) {
                int r0 = warpM*32 + m*16;
                const __nv_bfloat16* p0 = abuf + (r0 + g)*ASTR + ks*16 + tg*2;
                const __nv_bfloat16* p1 = abuf + (r0 + g + 8)*ASTR + ks*16 + tg*2;
                a[m][0] = *(const uint32_t*)p0;
                a[m][1] = *(const uint32_t*)p1;
                a[m][2] = *(const uint32_t*)(p0 + 8);
                a[m][3] = *(const uint32_t*)(p1 + 8);
            }
            #pragma unroll
            for (int j = 0; j < 12; j++) {
                int n0 = warpN*96 + j*8 + g;
                const __nv_bfloat16* pb = bbuf + n0*ASTR + ks*16 + tg*2;
                uint32_t b0 = *(const uint32_t*)pb;
                uint32_t b1 = *(const uint32_t*)(pb + 8);
                #pragma unroll
                for (int m = 0; m < 2; m++) {
                    asm volatile(
                        "mma.sync.aligned.m16n8k16.row.col.f32.bf16.bf16.f32 "
                        "{%0,%1,%2,%3}, {%4,%5,%6,%7}, {%8,%9}, {%0,%1,%2,%3};"
                        : "+f"(c[m][j][0]), "+f"(c[m][j][1]),
                          "+f"(c[m][j][2]), "+f"(c[m][j][3])
                        : "r"(a[m][0]), "r"(a[m][1]), "r"(a[m][2]), "r"(a[m][3]),
                          "r"(b0), "r"(b1));
                }
            }
        }
        __syncthreads();
    }

    #pragma unroll
    for (int m = 0; m < 2; m++) {
        int r0 = bm + warpM*32 + m*16 + g;
        #pragma unroll
        for (int j = 0; j < 12; j++) {
            int col = warpN*96 + j*8 + tg*2;
            if (r0 < Nn) {
                d_y[(size_t)r0*192 + col]     = c[m][j][0];
                d_y[(size_t)r0*192 + col + 1] = c[m][j][1];
            }
            if (r0 + 8 < Nn) {
                d_y[(size_t)(r0+8)*192 + col]     = c[m][j][2];
                d_y[(size_t)(r0+8)*192 + col + 1] = c[m][j][3];
            }
        }
    }
}

// fused combine (cvec/amp/att/bias) + BN statistics accumulation
__global__ __launch_bounds__(256) void k_combine_bn(const float* __restrict__ convb, int l) {
    __shared__ float sm1[256], sm2[256];
    int t = threadIdx.x;
    int col = t & 63, rg = t >> 6;
    float cv0 = d_cvec[col], cv1 = d_cvec[64 + col], cv2 = d_cvec[128 + col];
    float bias = convb[l*64 + col];
    float s = 0.f, ss = 0.f;
    for (int r = blockIdx.x*4 + rg; r < Nn; r += gridDim.x*4) {
        size_t b = (size_t)r*192;
        float y0 = d_y[b + col]       + cv0;
        float y1 = d_y[b + 64 + col]  + cv1;
        float y2 = d_y[b + 128 + col] + cv2;
        float h = y0 + d_amp[r]*y1 + d_att[r]*y2 + bias;
        d_h[(size_t)r*64 + col] = h;
        s += h; ss += h*h;
    }
    sm1[t] = s; sm2[t] = ss; __syncthreads();
    if (t < 64) {
        float a = sm1[t] + sm1[t+64] + sm1[t+128] + sm1[t+192];
        float c = sm2[t] + sm2[t+64] + sm2[t+128] + sm2[t+192];
        atomicAdd(&d_bnsum[l*64 + t], a);
        atomicAdd(&d_bnss[l*64 + t], c);
    }
}

__global__ __launch_bounds__(256) void k_bnapply(const float* __restrict__ g,
                                                 const float* __restrict__ b, int l) {
    int i = blockIdx.x*blockDim.x + threadIdx.x;
    if (i >= Nn*64) return;
    int j = i & 63;
    float mu  = d_bnsum[l*64 + j] / (float)Nn;
    float var = d_bnss[l*64 + j] / (float)Nn - mu*mu;
    float h = (d_h[i] - mu) * rsqrtf(var + 1e-5f) * g[l*64 + j] + b[l*64 + j];
    d_x[i] = fmaxf(h, 0.f) + d_x[i];
}

// ---------------- readout ----------------
__global__ __launch_bounds__(256) void k_pool(const int* __restrict__ batch) {
    int i = blockIdx.x*blockDim.x + threadIdx.x;
    if (i >= Nn*64) return;
    int n = i >> 6, j = i & 63;
    int bg = batch[n];
    atomicAdd(&d_pool[bg*64 + j], d_x[i]);
    if (j == 0) atomicAdd(&d_cntg[bg], 1.f);
}

__global__ __launch_bounds__(256) void k_final(const float* __restrict__ f1w,
                        const float* __restrict__ f1b,
                        const float* __restrict__ f2w, const float* __restrict__ f2b,
                        const float* __restrict__ f3w, const float* __restrict__ f3b,
                        float* __restrict__ out) {
    __shared__ float G[64*64], H1[64*32], H2[64*16];
    int t = threadIdx.x;
    for (int i = t; i < 4096; i += 256) {
        int g = i >> 6;
        G[i] = d_pool[i] / fmaxf(d_cntg[g], 1.f);
    }
    __syncthreads();
    for (int i = t; i < 2048; i += 256) {
        int g = i >> 5, o = i & 31;
        float s = f1b[o];
        #pragma unroll
        for (int k = 0; k < 64; k++) s += G[g*64 + k]*f1w[k*32 + o];
        H1[i] = fmaxf(s, 0.f);
    }
    __syncthreads();
    for (int i = t; i < 1024; i += 256) {
        int g = i >> 4, o = i & 15;
        float s = f2b[o];
        #pragma unroll
        for (int k = 0; k < 32; k++) s += H1[g*32 + k]*f2w[k*16 + o];
        H2[i] = fmaxf(s, 0.f);
    }
    __syncthreads();
    for (int i = t; i < 640; i += 256) {
        int g = i/10, o = i%10;
        float s = f3b[o];
        #pragma unroll
        for (int k = 0; k < 16; k++) s += H2[g*16 + k]*f3w[k*10 + o];
        out[i] = s;
    }
}

// ---------------- launch ----------------
extern "C" void kernel_launch(void* const* d_in, const int* in_sizes, int n_in,
                              void* d_out, int out_size) {
    const float* x      = (const float*)d_in[0];
    const int*   ei     = (const int*)  d_in[1];
    const int*   batch  = (const int*)  d_in[2];
    const float* eattr  = (const float*)d_in[3];
    const float* node_w = (const float*)d_in[4];
    const float* node_b = (const float*)d_in[5];
    const float* edge_w = (const float*)d_in[6];
    const float* edge_b = (const float*)d_in[7];
    const float* conv_w = (const float*)d_in[8];
    const float* conv_b = (const float*)d_in[9];
    const float* bn_g   = (const float*)d_in[10];
    const float* bn_b   = (const float*)d_in[11];
    const float* f1w    = (const float*)d_in[12];
    const float* f1b    = (const float*)d_in[13];
    const float* f2w    = (const float*)d_in[14];
    const float* f2b    = (const float*)d_in[15];
    const float* f3w    = (const float*)d_in[16];
    const float* f3b    = (const float*)d_in[17];
    float* out = (float*)d_out;

    const int* src = ei;
    const int* dst = ei + Ee;

    static int smset = 0;
    if (!smset) {
        cudaFuncSetAttribute(k_gemm_mma, cudaFuncAttributeMaxDynamicSharedMemorySize, SMEM_GEMM);
        smset = 1;
    }

    k_zero<<<(Nn + 255)/256, 256>>>();
    k_node_enc<<<(Nn + 3)/4, 256>>>(x, node_w, node_b);
    k_deg<<<(Ee + 255)/256, 256>>>(dst);
    k_scan1<<<SCB, 256>>>();
    k_scan2<<<1, 256>>>();
    k_scan3<<<SCB, 256>>>();
    k_sort<<<(Ee + 255)/256, 256>>>(src, dst);
    k_ea_enc<<<(Ee + 3)/4, 256>>>(eattr, edge_w, edge_b);
    k_amp<<<(Nn + 255)/256, 256>>>();

    for (int l = 0; l < NLAY; l++) {
        k_agg<<<Nn, 128>>>();
        k_prepB<<<192, 64>>>(conv_w, l);
        k_gemm_mma<<<MTILES, 256, SMEM_GEMM>>>();
        k_combine_bn<<<128, 256>>>(conv_b, l);
        k_bnapply<<<(Nn*64 + 255)/256, 256>>>(bn_g, bn_b, l);
    }

    k_pool<<<(Nn*64 + 255)/256, 256>>>(batch);
    k_final<<<1, 256>>>(f1w, f1b, f2w, f2b, f3w, f3b, out);
}

// round 13
// speedup vs baseline: 1.4405x; 1.2350x over previous
#include <cuda_runtime.h>
#include <cuda_fp16.h>
#include <math.h>
#include <stdint.h>

#define Nn 50000
#define Ee 800000
#define HID 64
#define EAD 16
#define NLAY 3
#define NCLS 10
#define NGR 64
#define KTOT 576
#define MTILES ((Nn + 127)/128)
#define SCB ((Nn + 255)/256)          // 196 scan blocks

// ---------------- static scratch ----------------
__device__ float d_x[(size_t)Nn*HID];
__device__ float d_ea[(size_t)Ee*HID];
__device__ int   d_srcs[Ee];
__device__ int   d_eperm[Ee];
__device__ int   d_degi[Nn];
__device__ int   d_off[Nn+1];
__device__ int   d_cursor[Nn];
__device__ int   d_bsum[SCB];
__device__ int   d_boff[SCB];
__device__ float d_amp[Nn], d_att[Nn];
__device__ float d_avglog;
__device__ __align__(16) __half d_aggA[(size_t)Nn*KTOT];
__device__ __align__(16) __half d_BH[(size_t)192*KTOT];
__device__ __align__(16) __half d_BL[(size_t)192*KTOT];
__device__ float d_cvec[192];
__device__ float d_y[(size_t)Nn*192];
__device__ float d_h[(size_t)Nn*HID];
__device__ float d_bnsum[HID], d_bnss[HID];
__device__ float d_pool[NGR*HID];
__device__ float d_cntg[NGR];

// ---------------- setup kernels ----------------
__global__ __launch_bounds__(256) void k_zero() {
    int i = blockIdx.x*blockDim.x + threadIdx.x;
    if (i < Nn) { d_degi[i] = 0; d_cursor[i] = 0; }
    if (i < NGR*HID) d_pool[i] = 0.f;
    if (i < NGR) d_cntg[i] = 0.f;
    if (i == 0) { d_avglog = 0.f; d_off[Nn] = Ee; }
}

__global__ __launch_bounds__(256) void k_node_enc(const float* __restrict__ x,
                           const float* __restrict__ w, const float* __restrict__ b) {
    __shared__ float Ws[64*64];
    __shared__ float xs[4][64];
    int t = threadIdx.x;
    for (int i = t; i < 4096; i += 256) Ws[i] = w[i];
    int r = t >> 6, c = t & 63;
    int n = blockIdx.x*4 + r;
    if (n < Nn) xs[r][c] = x[(size_t)n*64 + c];
    __syncthreads();
    if (n < Nn) {
        float s = b[c];
        #pragma unroll
        for (int k = 0; k < 64; k++) s += xs[r][k]*Ws[k*64 + c];
        d_x[(size_t)n*64 + c] = s;
    }
}

__global__ __launch_bounds__(256) void k_deg(const int* __restrict__ dst) {
    int e = blockIdx.x*blockDim.x + threadIdx.x;
    if (e < Ee) atomicAdd(&d_degi[dst[e]], 1);
}

// scan pass 1: per-block degree sums + avg-log reduction
__global__ __launch_bounds__(256) void k_scan1() {
    __shared__ int si[256];
    __shared__ float sl[256];
    int t = threadIdx.x;
    int i = blockIdx.x*256 + t;
    int d = (i < Nn) ? d_degi[i] : 0;
    si[t] = d;
    sl[t] = (i < Nn) ? logf((float)d + 1.f) : 0.f;
    __syncthreads();
    for (int o = 128; o > 0; o >>= 1) {
        if (t < o) { si[t] += si[t+o]; sl[t] += sl[t+o]; }
        __syncthreads();
    }
    if (t == 0) {
        d_bsum[blockIdx.x] = si[0];
        atomicAdd(&d_avglog, sl[0]);
    }
}

// scan pass 2: exclusive scan of SCB block sums (1 block)
__global__ __launch_bounds__(256) void k_scan2() {
    __shared__ int sm[256];
    int t = threadIdx.x;
    int v = (t < SCB) ? d_bsum[t] : 0;
    sm[t] = v; __syncthreads();
    for (int o = 1; o < 256; o <<= 1) {
        int u = (t >= o) ? sm[t-o] : 0;
        __syncthreads();
        sm[t] += u;
        __syncthreads();
    }
    if (t < SCB) d_boff[t] = sm[t] - v;
}

// scan pass 3: local exclusive scan + block offset
__global__ __launch_bounds__(256) void k_scan3() {
    __shared__ int sm[256];
    int t = threadIdx.x;
    int i = blockIdx.x*256 + t;
    int d = (i < Nn) ? d_degi[i] : 0;
    sm[t] = d; __syncthreads();
    for (int o = 1; o < 256; o <<= 1) {
        int u = (t >= o) ? sm[t-o] : 0;
        __syncthreads();
        sm[t] += u;
        __syncthreads();
    }
    if (i < Nn) d_off[i] = sm[t] - d + d_boff[blockIdx.x];
}

__global__ __launch_bounds__(256) void k_sort(const int* __restrict__ src,
                                              const int* __restrict__ dst) {
    int e = blockIdx.x*blockDim.x + threadIdx.x;
    if (e < Ee) {
        int d = dst[e];
        int r = atomicAdd(&d_cursor[d], 1);
        int pos = d_off[d] + r;
        d_srcs[pos]  = src[e];
        d_eperm[pos] = e;
    }
}

__global__ __launch_bounds__(256) void k_ea_enc(const float* __restrict__ ea,
                         const float* __restrict__ w, const float* __restrict__ b) {
    __shared__ float Ws[16*64];
    __shared__ float es[4][16];
    int t = threadIdx.x;
    for (int i = t; i < 1024; i += 256) Ws[i] = w[i];
    int r = t >> 6, c = t & 63;
    int p = blockIdx.x*4 + r;
    if (p < Ee && c < 16) {
        int e = d_eperm[p];
        es[r][c] = ea[(size_t)e*EAD + c];
    }
    __syncthreads();
    if (p < Ee) {
        float s = b[c];
        #pragma unroll
        for (int k = 0; k < 16; k++) s += es[r][k]*Ws[k*64 + c];
        d_ea[(size_t)p*64 + c] = s;
    }
}

__global__ __launch_bounds__(256) void k_amp() {
    int n = blockIdx.x*blockDim.x + threadIdx.x;
    if (n < Nn) {
        float degc = fmaxf((float)d_degi[n], 1.f);
        float ld = logf(degc + 1.f);
        float avg = d_avglog / (float)Nn;
        d_amp[n] = ld/avg;
        d_att[n] = avg/ld;
    }
}

// ---------------- per-layer kernels ----------------
// edge aggregation + fold: A = [mean|mn|mx|std of (src,ea) (512) | masked x (64)], fp16
__global__ __launch_bounds__(128) void k_agg() {
    int n = blockIdx.x;
    int t = threadIdx.x;            // 0..127
    int e0 = d_off[n], e1 = d_off[n+1];
    float s = 0.f, ss = 0.f, mx = -3.4e38f, mn = 3.4e38f;
    for (int p = e0; p < e1; p++) {
        float v;
        if (t < 64) {
            int sn = d_srcs[p];
            v = d_x[(size_t)sn*64 + t];
        } else {
            v = d_ea[(size_t)p*64 + (t - 64)];
        }
        s += v; ss += v*v;
        mx = fmaxf(mx, v); mn = fminf(mn, v);
    }
    int deg = e1 - e0;
    float inv = 1.f / fmaxf((float)deg, 1.f);
    float mean = s*inv;
    float msq  = ss*inv;
    float sd   = sqrtf(fmaxf(msq - mean*mean, 0.f) + 1e-5f);
    if (deg == 0) { mx = 0.f; mn = 0.f; }
    size_t b = (size_t)n*KTOT + t;
    d_aggA[b]       = __float2half(mean);
    d_aggA[b + 128] = __float2half(mn);
    d_aggA[b + 256] = __float2half(mx);
    d_aggA[b + 384] = __float2half(sd);
    if (t < 64) {
        float m2 = (deg > 0) ? d_x[(size_t)n*64 + t] : 0.f;
        d_aggA[(size_t)n*KTOT + 512 + t] = __float2half(m2);
    }
}

// folded B [192 x 576] fp16 hi/lo (row = output col; layout Bt[n][k]) + cvec
__global__ __launch_bounds__(64) void k_prepB(const float* __restrict__ convw, int l) {
    int c = blockIdx.x;             // 0..191 output column
    int tch = c >> 6, cc = c & 63;
    const float* W = convw + ((size_t)l*2304 + (size_t)tch*768)*64;
    const int LUT[8] = {64,128,256,320,448,512,640,704};
    for (int k = threadIdx.x; k < KTOT; k += 64) {
        float v;
        if (k < 512) {
            v = W[(size_t)(LUT[k >> 6] + (k & 63))*64 + cc];
        } else {
            int r = k - 512;
            v = W[(size_t)r*64 + cc] + W[(size_t)(192 + r)*64 + cc] + W[(size_t)(384 + r)*64 + cc];
        }
        __half h = __float2half(v);
        d_BH[(size_t)c*KTOT + k] = h;
        d_BL[(size_t)c*KTOT + k] = __float2half(v - __half2float(h));
    }
    if (threadIdx.x == 0) {
        float s = 0.f;
        for (int r = 0; r < 64; r++) s += W[(size_t)(576 + r)*64 + cc];
        d_cvec[c] = 0.0031622776601683794f * s;   // sqrt(1e-5) * sum(W_std_dst)
    }
}

// ------------- warp-mma fp16 GEMM: d_y[128 tile, 192] = A@(BH+BL), 2 combos -------------
#define ASTR 40                       // smem row stride in halves (conflict-free)
#define SMA_HALVES (128*ASTR)         // 5120
#define SMB_HALVES (192*ASTR)         // 7680
#define BUF_HALVES (SMA_HALVES + SMB_HALVES)   // 12800
#define SMEM_GEMM (2*BUF_HALVES*2)    // bytes = 51200

__global__ __launch_bounds__(256) void k_gemm_mma() {
    extern __shared__ __half smg[];
    int t = threadIdx.x;
    int lane = t & 31, warp = t >> 5;
    int warpM = warp & 3, warpN = warp >> 2;     // 4 x 2 warp grid
    int bm = blockIdx.x * 128;
    int g = lane >> 2, tg = lane & 3;

    float c[2][12][4];
    #pragma unroll
    for (int m = 0; m < 2; m++)
        #pragma unroll
        for (int j = 0; j < 12; j++)
            #pragma unroll
            for (int q = 0; q < 4; q++) c[m][j][q] = 0.f;

    int arow = t >> 1, akoff = (t & 1) * 16;     // A: 128 rows x 32 halves
    uint4 ra0, ra1, rb0, rb1, rb2;

    const int NIT = 36;                          // 2 combos x 18 chunks
    {
        int grow = bm + arow;
        if (grow < Nn) {
            const __half* p = d_aggA + (size_t)grow*KTOT + akoff;
            ra0 = *(const uint4*)p; ra1 = *(const uint4*)(p + 8);
        } else { ra0 = make_uint4(0,0,0,0); ra1 = ra0; }
        int u0 = t, u1 = t + 256, u2 = t + 512;
        rb0 = *(const uint4*)(d_BH + (size_t)(u0>>2)*KTOT + (u0&3)*8);
        rb1 = *(const uint4*)(d_BH + (size_t)(u1>>2)*KTOT + (u1&3)*8);
        rb2 = *(const uint4*)(d_BH + (size_t)(u2>>2)*KTOT + (u2&3)*8);
    }

    for (int it = 0; it < NIT; it++) {
        __half* buf  = smg + (it & 1)*BUF_HALVES;
        __half* abuf = buf;
        __half* bbuf = buf + SMA_HALVES;
        *(uint4*)(abuf + arow*ASTR + akoff)     = ra0;
        *(uint4*)(abuf + arow*ASTR + akoff + 8) = ra1;
        {
            int u0 = t, u1 = t + 256, u2 = t + 512;
            *(uint4*)(bbuf + (u0>>2)*ASTR + (u0&3)*8) = rb0;
            *(uint4*)(bbuf + (u1>>2)*ASTR + (u1&3)*8) = rb1;
            *(uint4*)(bbuf + (u2>>2)*ASTR + (u2&3)*8) = rb2;
        }
        __syncthreads();
        if (it + 1 < NIT) {
            int nit = it + 1;
            int combo = nit / 18, kc = nit % 18, k0 = kc * 32;
            const __half* Bs = combo ? d_BL : d_BH;
            int grow = bm + arow;
            if (grow < Nn) {
                const __half* p = d_aggA + (size_t)grow*KTOT + k0 + akoff;
                ra0 = *(const uint4*)p; ra1 = *(const uint4*)(p + 8);
            } else { ra0 = make_uint4(0,0,0,0); ra1 = ra0; }
            int u0 = t, u1 = t + 256, u2 = t + 512;
            rb0 = *(const uint4*)(Bs + (size_t)(u0>>2)*KTOT + k0 + (u0&3)*8);
            rb1 = *(const uint4*)(Bs + (size_t)(u1>>2)*KTOT + k0 + (u1&3)*8);
            rb2 = *(const uint4*)(Bs + (size_t)(u2>>2)*KTOT + k0 + (u2&3)*8);
        }
        #pragma unroll
        for (int ks = 0; ks < 2; ks++) {
            uint32_t a[2][4];
            #pragma unroll
            for (int m = 0; m < 2; m++) {
                int r0 = warpM*32 + m*16;
                const __half* p0 = abuf + (r0 + g)*ASTR + ks*16 + tg*2;
                const __half* p1 = abuf + (r0 + g + 8)*ASTR + ks*16 + tg*2;
                a[m][0] = *(const uint32_t*)p0;
                a[m][1] = *(const uint32_t*)p1;
                a[m][2] = *(const uint32_t*)(p0 + 8);
                a[m][3] = *(const uint32_t*)(p1 + 8);
            }
            #pragma unroll
            for (int j = 0; j < 12; j++) {
                int n0 = warpN*96 + j*8 + g;
                const __half* pb = bbuf + n0*ASTR + ks*16 + tg*2;
                uint32_t b0 = *(const uint32_t*)pb;
                uint32_t b1 = *(const uint32_t*)(pb + 8);
                #pragma unroll
                for (int m = 0; m < 2; m++) {
                    asm volatile(
                        "mma.sync.aligned.m16n8k16.row.col.f32.f16.f16.f32 "
                        "{%0,%1,%2,%3}, {%4,%5,%6,%7}, {%8,%9}, {%0,%1,%2,%3};"
                        : "+f"(c[m][j][0]), "+f"(c[m][j][1]),
                          "+f"(c[m][j][2]), "+f"(c[m][j][3])
                        : "r"(a[m][0]), "r"(a[m][1]), "r"(a[m][2]), "r"(a[m][3]),
                          "r"(b0), "r"(b1));
                }
            }
        }
        __syncthreads();
    }

    #pragma unroll
    for (int m = 0; m < 2; m++) {
        int r0 = bm + warpM*32 + m*16 + g;
        #pragma unroll
        for (int j = 0; j < 12; j++) {
            int col = warpN*96 + j*8 + tg*2;
            if (r0 < Nn) {
                d_y[(size_t)r0*192 + col]     = c[m][j][0];
                d_y[(size_t)r0*192 + col + 1] = c[m][j][1];
            }
            if (r0 + 8 < Nn) {
                d_y[(size_t)(r0+8)*192 + col]     = c[m][j][2];
                d_y[(size_t)(r0+8)*192 + col + 1] = c[m][j][3];
            }
        }
    }
}

__global__ __launch_bounds__(256) void k_combine(const float* __restrict__ convb, int l) {
    int i = blockIdx.x*blockDim.x + threadIdx.x;
    if (i >= Nn*64) return;
    int n = i >> 6, j = i & 63;
    size_t b = (size_t)n*192;
    float y0 = d_y[b + j]       + d_cvec[j];
    float y1 = d_y[b + 64 + j]  + d_cvec[64 + j];
    float y2 = d_y[b + 128 + j] + d_cvec[128 + j];
    d_h[i] = y0 + d_amp[n]*y1 + d_att[n]*y2 + convb[l*64 + j];
}

__global__ __launch_bounds__(128) void k_bnzero() {
    int t = threadIdx.x;
    if (t < HID) { d_bnsum[t] = 0.f; d_bnss[t] = 0.f; }
}

__global__ __launch_bounds__(256) void k_bnstat() {
    __shared__ float sm1[256], sm2[256];
    int t = threadIdx.x;
    int col = t & 63, rg = t >> 6;
    float s = 0.f, ss = 0.f;
    for (int r = blockIdx.x*4 + rg; r < Nn; r += gridDim.x*4) {
        float v = d_h[(size_t)r*64 + col];
        s += v; ss += v*v;
    }
    sm1[t] = s; sm2[t] = ss; __syncthreads();
    if (t < 64) {
        float a = sm1[t] + sm1[t+64] + sm1[t+128] + sm1[t+192];
        float c = sm2[t] + sm2[t+64] + sm2[t+128] + sm2[t+192];
        atomicAdd(&d_bnsum[t], a);
        atomicAdd(&d_bnss[t], c);
    }
}

__global__ __launch_bounds__(256) void k_bnapply(const float* __restrict__ g,
                                                 const float* __restrict__ b, int l) {
    int i = blockIdx.x*blockDim.x + threadIdx.x;
    if (i >= Nn*64) return;
    int j = i & 63;
    float mu  = d_bnsum[j] / (float)Nn;
    float var = d_bnss[j] / (float)Nn - mu*mu;
    float h = (d_h[i] - mu) * rsqrtf(var + 1e-5f) * g[l*64 + j] + b[l*64 + j];
    d_x[i] = fmaxf(h, 0.f) + d_x[i];
}

// ---------------- readout ----------------
__global__ __launch_bounds__(256) void k_pool(const int* __restrict__ batch) {
    int i = blockIdx.x*blockDim.x + threadIdx.x;
    if (i >= Nn*64) return;
    int n = i >> 6, j = i & 63;
    int bg = batch[n];
    atomicAdd(&d_pool[bg*64 + j], d_x[i]);
    if (j == 0) atomicAdd(&d_cntg[bg], 1.f);
}

__global__ __launch_bounds__(256) void k_final(const float* __restrict__ f1w,
                        const float* __restrict__ f1b,
                        const float* __restrict__ f2w, const float* __restrict__ f2b,
                        const float* __restrict__ f3w, const float* __restrict__ f3b,
                        float* __restrict__ out) {
    __shared__ float G[64*64], H1[64*32], H2[64*16];
    int t = threadIdx.x;
    for (int i = t; i < 4096; i += 256) {
        int g = i >> 6;
        G[i] = d_pool[i] / fmaxf(d_cntg[g], 1.f);
    }
    __syncthreads();
    for (int i = t; i < 2048; i += 256) {
        int g = i >> 5, o = i & 31;
        float s = f1b[o];
        #pragma unroll
        for (int k = 0; k < 64; k++) s += G[g*64 + k]*f1w[k*32 + o];
        H1[i] = fmaxf(s, 0.f);
    }
    __syncthreads();
    for (int i = t; i < 1024; i += 256) {
        int g = i >> 4, o = i & 15;
        float s = f2b[o];
        #pragma unroll
        for (int k = 0; k < 32; k++) s += H1[g*32 + k]*f2w[k*16 + o];
        H2[i] = fmaxf(s, 0.f);
    }
    __syncthreads();
    for (int i = t; i < 640; i += 256) {
        int g = i/10, o = i%10;
        float s = f3b[o];
        #pragma unroll
        for (int k = 0; k < 16; k++) s += H2[g*16 + k]*f3w[k*10 + o];
        out[i] = s;
    }
}

// ---------------- launch ----------------
extern "C" void kernel_launch(void* const* d_in, const int* in_sizes, int n_in,
                              void* d_out, int out_size) {
    const float* x      = (const float*)d_in[0];
    const int*   ei     = (const int*)  d_in[1];
    const int*   batch  = (const int*)  d_in[2];
    const float* eattr  = (const float*)d_in[3];
    const float* node_w = (const float*)d_in[4];
    const float* node_b = (const float*)d_in[5];
    const float* edge_w = (const float*)d_in[6];
    const float* edge_b = (const float*)d_in[7];
    const float* conv_w = (const float*)d_in[8];
    const float* conv_b = (const float*)d_in[9];
    const float* bn_g   = (const float*)d_in[10];
    const float* bn_b   = (const float*)d_in[11];
    const float* f1w    = (const float*)d_in[12];
    const float* f1b    = (const float*)d_in[13];
    const float* f2w    = (const float*)d_in[14];
    const float* f2b    = (const float*)d_in[15];
    const float* f3w    = (const float*)d_in[16];
    const float* f3b    = (const float*)d_in[17];
    float* out = (float*)d_out;

    const int* src = ei;
    const int* dst = ei + Ee;

    static int smset = 0;
    if (!smset) {
        cudaFuncSetAttribute(k_gemm_mma, cudaFuncAttributeMaxDynamicSharedMemorySize, SMEM_GEMM);
        smset = 1;
    }

    k_zero<<<(Nn + 255)/256, 256>>>();
    k_node_enc<<<(Nn + 3)/4, 256>>>(x, node_w, node_b);
    k_deg<<<(Ee + 255)/256, 256>>>(dst);
    k_scan1<<<SCB, 256>>>();
    k_scan2<<<1, 256>>>();
    k_scan3<<<SCB, 256>>>();
    k_sort<<<(Ee + 255)/256, 256>>>(src, dst);
    k_ea_enc<<<(Ee + 3)/4, 256>>>(eattr, edge_w, edge_b);
    k_amp<<<(Nn + 255)/256, 256>>>();

    for (int l = 0; l < NLAY; l++) {
        k_agg<<<Nn, 128>>>();
        k_prepB<<<192, 64>>>(conv_w, l);
        k_gemm_mma<<<MTILES, 256, SMEM_GEMM>>>();
        k_combine<<<(Nn*64 + 255)/256, 256>>>(conv_b, l);
        k_bnzero<<<1, 128>>>();
        k_bnstat<<<128, 256>>>();
        k_bnapply<<<(Nn*64 + 255)/256, 256>>>(bn_g, bn_b, l);
    }

    k_pool<<<(Nn*64 + 255)/256, 256>>>(batch);
    k_final<<<1, 256>>>(f1w, f1b, f2w, f2b, f3w, f3b, out);
}

// round 14
// speedup vs baseline: 1.6249x; 1.1280x over previous
#include <cuda_runtime.h>
#include <cuda_fp16.h>
#include <math.h>
#include <stdint.h>

#define Nn 50000
#define Ee 800000
#define HID 64
#define EAD 16
#define NLAY 3
#define NCLS 10
#define NGR 64
#define KTOT 576
#define MTILES ((Nn + 127)/128)
#define SCB ((Nn + 255)/256)          // 196 scan blocks

// ---------------- static scratch ----------------
__device__ float d_x[(size_t)Nn*HID];
__device__ float d_ea[(size_t)Ee*HID];
__device__ int   d_srcs[Ee];
__device__ int   d_eperm[Ee];
__device__ int   d_degi[Nn];
__device__ int   d_off[Nn+1];
__device__ int   d_cursor[Nn];
__device__ int   d_bsum[SCB];
__device__ int   d_boff[SCB];
__device__ float d_amp[Nn], d_att[Nn];
__device__ float d_avglog;
__device__ __align__(16) __half d_aggA[(size_t)Nn*KTOT];
__device__ __align__(16) __half d_BH[(size_t)192*KTOT];
__device__ __align__(16) __half d_BL[(size_t)192*KTOT];
__device__ float d_cvec[192];
__device__ float d_h[(size_t)Nn*HID];
__device__ float d_bnsum[HID], d_bnss[HID];
__device__ float d_pool[NGR*HID];
__device__ float d_cntg[NGR];

// ---------------- setup kernels ----------------
__global__ __launch_bounds__(256) void k_zero() {
    int i = blockIdx.x*blockDim.x + threadIdx.x;
    if (i < Nn) { d_degi[i] = 0; d_cursor[i] = 0; }
    if (i < NGR*HID) d_pool[i] = 0.f;
    if (i < NGR) d_cntg[i] = 0.f;
    if (i == 0) { d_avglog = 0.f; d_off[Nn] = Ee; }
}

__global__ __launch_bounds__(256) void k_node_enc(const float* __restrict__ x,
                           const float* __restrict__ w, const float* __restrict__ b) {
    __shared__ float Ws[64*64];
    __shared__ float xs[4][64];
    int t = threadIdx.x;
    for (int i = t; i < 4096; i += 256) Ws[i] = w[i];
    int r = t >> 6, c = t & 63;
    int n = blockIdx.x*4 + r;
    if (n < Nn) xs[r][c] = x[(size_t)n*64 + c];
    __syncthreads();
    if (n < Nn) {
        float s = b[c];
        #pragma unroll
        for (int k = 0; k < 64; k++) s += xs[r][k]*Ws[k*64 + c];
        d_x[(size_t)n*64 + c] = s;
    }
}

__global__ __launch_bounds__(256) void k_deg(const int* __restrict__ dst) {
    int e = blockIdx.x*blockDim.x + threadIdx.x;
    if (e < Ee) atomicAdd(&d_degi[dst[e]], 1);
}

// scan pass 1: per-block degree sums + avg-log reduction
__global__ __launch_bounds__(256) void k_scan1() {
    __shared__ int si[256];
    __shared__ float sl[256];
    int t = threadIdx.x;
    int i = blockIdx.x*256 + t;
    int d = (i < Nn) ? d_degi[i] : 0;
    si[t] = d;
    sl[t] = (i < Nn) ? logf((float)d + 1.f) : 0.f;
    __syncthreads();
    for (int o = 128; o > 0; o >>= 1) {
        if (t < o) { si[t] += si[t+o]; sl[t] += sl[t+o]; }
        __syncthreads();
    }
    if (t == 0) {
        d_bsum[blockIdx.x] = si[0];
        atomicAdd(&d_avglog, sl[0]);
    }
}

// scan pass 2: exclusive scan of SCB block sums (1 block)
__global__ __launch_bounds__(256) void k_scan2() {
    __shared__ int sm[256];
    int t = threadIdx.x;
    int v = (t < SCB) ? d_bsum[t] : 0;
    sm[t] = v; __syncthreads();
    for (int o = 1; o < 256; o <<= 1) {
        int u = (t >= o) ? sm[t-o] : 0;
        __syncthreads();
        sm[t] += u;
        __syncthreads();
    }
    if (t < SCB) d_boff[t] = sm[t] - v;
}

// scan pass 3: local exclusive scan + block offset
__global__ __launch_bounds__(256) void k_scan3() {
    __shared__ int sm[256];
    int t = threadIdx.x;
    int i = blockIdx.x*256 + t;
    int d = (i < Nn) ? d_degi[i] : 0;
    sm[t] = d; __syncthreads();
    for (int o = 1; o < 256; o <<= 1) {
        int u = (t >= o) ? sm[t-o] : 0;
        __syncthreads();
        sm[t] += u;
        __syncthreads();
    }
    if (i < Nn) d_off[i] = sm[t] - d + d_boff[blockIdx.x];
}

__global__ __launch_bounds__(256) void k_sort(const int* __restrict__ src,
                                              const int* __restrict__ dst) {
    int e = blockIdx.x*blockDim.x + threadIdx.x;
    if (e < Ee) {
        int d = dst[e];
        int r = atomicAdd(&d_cursor[d], 1);
        int pos = d_off[d] + r;
        d_srcs[pos]  = src[e];
        d_eperm[pos] = e;
    }
}

__global__ __launch_bounds__(256) void k_ea_enc(const float* __restrict__ ea,
                         const float* __restrict__ w, const float* __restrict__ b) {
    __shared__ float Ws[16*64];
    __shared__ float es[4][16];
    int t = threadIdx.x;
    for (int i = t; i < 1024; i += 256) Ws[i] = w[i];
    int r = t >> 6, c = t & 63;
    int p = blockIdx.x*4 + r;
    if (p < Ee && c < 16) {
        int e = d_eperm[p];
        es[r][c] = ea[(size_t)e*EAD + c];
    }
    __syncthreads();
    if (p < Ee) {
        float s = b[c];
        #pragma unroll
        for (int k = 0; k < 16; k++) s += es[r][k]*Ws[k*64 + c];
        d_ea[(size_t)p*64 + c] = s;
    }
}

// ONCE: ea-side segment stats (layer-invariant) -> ea columns of d_aggA
__global__ __launch_bounds__(64) void k_ea_stat() {
    int n = blockIdx.x;
    int c = threadIdx.x;             // 0..63
    int e0 = d_off[n], e1 = d_off[n+1];
    float s = 0.f, ss = 0.f, mx = -3.4e38f, mn = 3.4e38f;
    for (int p = e0; p < e1; p++) {
        float v = d_ea[(size_t)p*64 + c];
        s += v; ss += v*v;
        mx = fmaxf(mx, v); mn = fminf(mn, v);
    }
    int deg = e1 - e0;
    float inv = 1.f / fmaxf((float)deg, 1.f);
    float mean = s*inv;
    float sd   = sqrtf(fmaxf(ss*inv - mean*mean, 0.f) + 1e-5f);
    if (deg == 0) { mx = 0.f; mn = 0.f; }
    size_t b = (size_t)n*KTOT + 64 + c;
    d_aggA[b]       = __float2half(mean);
    d_aggA[b + 128] = __float2half(mn);
    d_aggA[b + 256] = __float2half(mx);
    d_aggA[b + 384] = __float2half(sd);
}

__global__ __launch_bounds__(256) void k_amp() {
    int n = blockIdx.x*blockDim.x + threadIdx.x;
    if (n < Nn) {
        float degc = fmaxf((float)d_degi[n], 1.f);
        float ld = logf(degc + 1.f);
        float avg = d_avglog / (float)Nn;
        d_amp[n] = ld/avg;
        d_att[n] = avg/ld;
    }
}

// ---------------- per-layer kernels ----------------
// x-src side stats + masked x (2 nodes/block, 128 threads)
__global__ __launch_bounds__(128) void k_xagg() {
    int t = threadIdx.x;
    int sub = t >> 6, c = t & 63;
    int n = blockIdx.x*2 + sub;
    if (n >= Nn) return;
    int e0 = d_off[n], e1 = d_off[n+1];
    float s = 0.f, ss = 0.f, mx = -3.4e38f, mn = 3.4e38f;
    for (int p = e0; p < e1; p++) {
        float v = d_x[(size_t)d_srcs[p]*64 + c];
        s += v; ss += v*v;
        mx = fmaxf(mx, v); mn = fminf(mn, v);
    }
    int deg = e1 - e0;
    float inv = 1.f / fmaxf((float)deg, 1.f);
    float mean = s*inv;
    float sd   = sqrtf(fmaxf(ss*inv - mean*mean, 0.f) + 1e-5f);
    if (deg == 0) { mx = 0.f; mn = 0.f; }
    size_t b = (size_t)n*KTOT + c;
    d_aggA[b]       = __float2half(mean);
    d_aggA[b + 128] = __float2half(mn);
    d_aggA[b + 256] = __float2half(mx);
    d_aggA[b + 384] = __float2half(sd);
    float m2 = (deg > 0) ? d_x[(size_t)n*64 + c] : 0.f;
    d_aggA[(size_t)n*KTOT + 512 + c] = __float2half(m2);
}

// folded B [192 x 576] fp16 hi/lo (row = output col; layout Bt[n][k]) + cvec
__global__ __launch_bounds__(64) void k_prepB(const float* __restrict__ convw, int l) {
    int c = blockIdx.x;             // 0..191 output column
    int tch = c >> 6, cc = c & 63;
    const float* W = convw + ((size_t)l*2304 + (size_t)tch*768)*64;
    const int LUT[8] = {64,128,256,320,448,512,640,704};
    for (int k = threadIdx.x; k < KTOT; k += 64) {
        float v;
        if (k < 512) {
            v = W[(size_t)(LUT[k >> 6] + (k & 63))*64 + cc];
        } else {
            int r = k - 512;
            v = W[(size_t)r*64 + cc] + W[(size_t)(192 + r)*64 + cc] + W[(size_t)(384 + r)*64 + cc];
        }
        __half h = __float2half(v);
        d_BH[(size_t)c*KTOT + k] = h;
        d_BL[(size_t)c*KTOT + k] = __float2half(v - __half2float(h));
    }
    if (threadIdx.x == 0) {
        float s = 0.f;
        for (int r = 0; r < 64; r++) s += W[(size_t)(576 + r)*64 + cc];
        d_cvec[c] = 0.0031622776601683794f * s;   // sqrt(1e-5) * sum(W_std_dst)
    }
}

// --- warp-mma fp16 GEMM + fused combine epilogue -> d_h directly ---
#define ASTR 40                       // smem row stride in halves (conflict-free)
#define SMA_HALVES (128*ASTR)         // 5120
#define SMB_HALVES (192*ASTR)         // 7680
#define BUF_HALVES (SMA_HALVES + SMB_HALVES)   // 12800
#define SMEM_GEMM (2*BUF_HALVES*2)    // bytes = 51200
#define YSTR 196                      // fp32 epilogue stage stride

__global__ __launch_bounds__(256) void k_gemm_mma(const float* __restrict__ convb, int l) {
    extern __shared__ __half smg[];
    int t = threadIdx.x;
    int lane = t & 31, warp = t >> 5;
    int warpM = warp & 3, warpN = warp >> 2;     // 4 x 2 warp grid
    int bm = blockIdx.x * 128;
    int g = lane >> 2, tg = lane & 3;

    float c[2][12][4];
    #pragma unroll
    for (int m = 0; m < 2; m++)
        #pragma unroll
        for (int j = 0; j < 12; j++)
            #pragma unroll
            for (int q = 0; q < 4; q++) c[m][j][q] = 0.f;

    int arow = t >> 1, akoff = (t & 1) * 16;     // A: 128 rows x 32 halves
    uint4 ra0, ra1, rb0, rb1, rb2;

    const int NIT = 36;                          // 2 combos x 18 chunks
    {
        int grow = bm + arow;
        if (grow < Nn) {
            const __half* p = d_aggA + (size_t)grow*KTOT + akoff;
            ra0 = *(const uint4*)p; ra1 = *(const uint4*)(p + 8);
        } else { ra0 = make_uint4(0,0,0,0); ra1 = ra0; }
        int u0 = t, u1 = t + 256, u2 = t + 512;
        rb0 = *(const uint4*)(d_BH + (size_t)(u0>>2)*KTOT + (u0&3)*8);
        rb1 = *(const uint4*)(d_BH + (size_t)(u1>>2)*KTOT + (u1&3)*8);
        rb2 = *(const uint4*)(d_BH + (size_t)(u2>>2)*KTOT + (u2&3)*8);
    }

    for (int it = 0; it < NIT; it++) {
        __half* buf  = smg + (it & 1)*BUF_HALVES;
        __half* abuf = buf;
        __half* bbuf = buf + SMA_HALVES;
        *(uint4*)(abuf + arow*ASTR + akoff)     = ra0;
        *(uint4*)(abuf + arow*ASTR + akoff + 8) = ra1;
        {
            int u0 = t, u1 = t + 256, u2 = t + 512;
            *(uint4*)(bbuf + (u0>>2)*ASTR + (u0&3)*8) = rb0;
            *(uint4*)(bbuf + (u1>>2)*ASTR + (u1&3)*8) = rb1;
            *(uint4*)(bbuf + (u2>>2)*ASTR + (u2&3)*8) = rb2;
        }
        __syncthreads();
        if (it + 1 < NIT) {
            int nit = it + 1;
            int combo = nit / 18, kc = nit % 18, k0 = kc * 32;
            const __half* Bs = combo ? d_BL : d_BH;
            int grow = bm + arow;
            if (grow < Nn) {
                const __half* p = d_aggA + (size_t)grow*KTOT + k0 + akoff;
                ra0 = *(const uint4*)p; ra1 = *(const uint4*)(p + 8);
            } else { ra0 = make_uint4(0,0,0,0); ra1 = ra0; }
            int u0 = t, u1 = t + 256, u2 = t + 512;
            rb0 = *(const uint4*)(Bs + (size_t)(u0>>2)*KTOT + k0 + (u0&3)*8);
            rb1 = *(const uint4*)(Bs + (size_t)(u1>>2)*KTOT + k0 + (u1&3)*8);
            rb2 = *(const uint4*)(Bs + (size_t)(u2>>2)*KTOT + k0 + (u2&3)*8);
        }
        #pragma unroll
        for (int ks = 0; ks < 2; ks++) {
            uint32_t a[2][4];
            #pragma unroll
            for (int m = 0; m < 2; m++) {
                int r0 = warpM*32 + m*16;
                const __half* p0 = abuf + (r0 + g)*ASTR + ks*16 + tg*2;
                const __half* p1 = abuf + (r0 + g + 8)*ASTR + ks*16 + tg*2;
                a[m][0] = *(const uint32_t*)p0;
                a[m][1] = *(const uint32_t*)p1;
                a[m][2] = *(const uint32_t*)(p0 + 8);
                a[m][3] = *(const uint32_t*)(p1 + 8);
            }
            #pragma unroll
            for (int j = 0; j < 12; j++) {
                int n0 = warpN*96 + j*8 + g;
                const __half* pb = bbuf + n0*ASTR + ks*16 + tg*2;
                uint32_t b0 = *(const uint32_t*)pb;
                uint32_t b1 = *(const uint32_t*)(pb + 8);
                #pragma unroll
                for (int m = 0; m < 2; m++) {
                    asm volatile(
                        "mma.sync.aligned.m16n8k16.row.col.f32.f16.f16.f32 "
                        "{%0,%1,%2,%3}, {%4,%5,%6,%7}, {%8,%9}, {%0,%1,%2,%3};"
                        : "+f"(c[m][j][0]), "+f"(c[m][j][1]),
                          "+f"(c[m][j][2]), "+f"(c[m][j][3])
                        : "r"(a[m][0]), "r"(a[m][1]), "r"(a[m][2]), "r"(a[m][3]),
                          "r"(b0), "r"(b1));
                }
            }
        }
        __syncthreads();
    }

    // fused epilogue: stage C through smem in two 64-row halves, combine, write d_h
    float* ysm = (float*)smg;
    int ecol = t & 63;
    int erow0 = t >> 6;               // 0..3
    float cv0 = d_cvec[ecol], cv1 = d_cvec[64 + ecol], cv2 = d_cvec[128 + ecol];
    float bias = convb[l*64 + ecol];
    #pragma unroll
    for (int half = 0; half < 2; half++) {
        if (half) __syncthreads();    // protect smem between halves
        if ((warpM >> 1) == half) {
            int lr = (warpM & 1)*32;
            #pragma unroll
            for (int m = 0; m < 2; m++) {
                int lrow = lr + m*16 + g;
                #pragma unroll
                for (int j = 0; j < 12; j++) {
                    int col = warpN*96 + j*8 + tg*2;
                    ysm[lrow*YSTR + col]         = c[m][j][0];
                    ysm[lrow*YSTR + col + 1]     = c[m][j][1];
                    ysm[(lrow+8)*YSTR + col]     = c[m][j][2];
                    ysm[(lrow+8)*YSTR + col + 1] = c[m][j][3];
                }
            }
        }
        __syncthreads();
        #pragma unroll
        for (int q = 0; q < 16; q++) {
            int row = erow0 + q*4;
            int n = bm + half*64 + row;
            if (n < Nn) {
                float y0 = ysm[row*YSTR + ecol]       + cv0;
                float y1 = ysm[row*YSTR + 64 + ecol]  + cv1;
                float y2 = ysm[row*YSTR + 128 + ecol] + cv2;
                d_h[(size_t)n*64 + ecol] = y0 + d_amp[n]*y1 + d_att[n]*y2 + bias;
            }
        }
    }
}

__global__ __launch_bounds__(128) void k_bnzero() {
    int t = threadIdx.x;
    if (t < HID) { d_bnsum[t] = 0.f; d_bnss[t] = 0.f; }
}

__global__ __launch_bounds__(256) void k_bnstat() {
    __shared__ float sm1[256], sm2[256];
    int t = threadIdx.x;
    int col = t & 63, rg = t >> 6;
    float s = 0.f, ss = 0.f;
    for (int r = blockIdx.x*4 + rg; r < Nn; r += gridDim.x*4) {
        float v = d_h[(size_t)r*64 + col];
        s += v; ss += v*v;
    }
    sm1[t] = s; sm2[t] = ss; __syncthreads();
    if (t < 64) {
        float a = sm1[t] + sm1[t+64] + sm1[t+128] + sm1[t+192];
        float c = sm2[t] + sm2[t+64] + sm2[t+128] + sm2[t+192];
        atomicAdd(&d_bnsum[t], a);
        atomicAdd(&d_bnss[t], c);
    }
}

__global__ __launch_bounds__(256) void k_bnapply(const float* __restrict__ g,
                                                 const float* __restrict__ b, int l) {
    int i = blockIdx.x*blockDim.x + threadIdx.x;
    if (i >= Nn*64) return;
    int j = i & 63;
    float mu  = d_bnsum[j] / (float)Nn;
    float var = d_bnss[j] / (float)Nn - mu*mu;
    float h = (d_h[i] - mu) * rsqrtf(var + 1e-5f) * g[l*64 + j] + b[l*64 + j];
    d_x[i] = fmaxf(h, 0.f) + d_x[i];
}

// ---------------- readout ----------------
__global__ __launch_bounds__(256) void k_pool(const int* __restrict__ batch) {
    int i = blockIdx.x*blockDim.x + threadIdx.x;
    if (i >= Nn*64) return;
    int n = i >> 6, j = i & 63;
    int bg = batch[n];
    atomicAdd(&d_pool[bg*64 + j], d_x[i]);
    if (j == 0) atomicAdd(&d_cntg[bg], 1.f);
}

__global__ __launch_bounds__(256) void k_final(const float* __restrict__ f1w,
                        const float* __restrict__ f1b,
                        const float* __restrict__ f2w, const float* __restrict__ f2b,
                        const float* __restrict__ f3w, const float* __restrict__ f3b,
                        float* __restrict__ out) {
    __shared__ float G[64*64], H1[64*32], H2[64*16];
    int t = threadIdx.x;
    for (int i = t; i < 4096; i += 256) {
        int g = i >> 6;
        G[i] = d_pool[i] / fmaxf(d_cntg[g], 1.f);
    }
    __syncthreads();
    for (int i = t; i < 2048; i += 256) {
        int g = i >> 5, o = i & 31;
        float s = f1b[o];
        #pragma unroll
        for (int k = 0; k < 64; k++) s += G[g*64 + k]*f1w[k*32 + o];
        H1[i] = fmaxf(s, 0.f);
    }
    __syncthreads();
    for (int i = t; i < 1024; i += 256) {
        int g = i >> 4, o = i & 15;
        float s = f2b[o];
        #pragma unroll
        for (int k = 0; k < 32; k++) s += H1[g*32 + k]*f2w[k*16 + o];
        H2[i] = fmaxf(s, 0.f);
    }
    __syncthreads();
    for (int i = t; i < 640; i += 256) {
        int g = i/10, o = i%10;
        float s = f3b[o];
        #pragma unroll
        for (int k = 0; k < 16; k++) s += H2[g*16 + k]*f3w[k*10 + o];
        out[i] = s;
    }
}

// ---------------- launch ----------------
extern "C" void kernel_launch(void* const* d_in, const int* in_sizes, int n_in,
                              void* d_out, int out_size) {
    const float* x      = (const float*)d_in[0];
    const int*   ei     = (const int*)  d_in[1];
    const int*   batch  = (const int*)  d_in[2];
    const float* eattr  = (const float*)d_in[3];
    const float* node_w = (const float*)d_in[4];
    const float* node_b = (const float*)d_in[5];
    const float* edge_w = (const float*)d_in[6];
    const float* edge_b = (const float*)d_in[7];
    const float* conv_w = (const float*)d_in[8];
    const float* conv_b = (const float*)d_in[9];
    const float* bn_g   = (const float*)d_in[10];
    const float* bn_b   = (const float*)d_in[11];
    const float* f1w    = (const float*)d_in[12];
    const float* f1b    = (const float*)d_in[13];
    const float* f2w    = (const float*)d_in[14];
    const float* f2b    = (const float*)d_in[15];
    const float* f3w    = (const float*)d_in[16];
    const float* f3b    = (const float*)d_in[17];
    float* out = (float*)d_out;

    const int* src = ei;
    const int* dst = ei + Ee;

    static int smset = 0;
    if (!smset) {
        cudaFuncSetAttribute(k_gemm_mma, cudaFuncAttributeMaxDynamicSharedMemorySize, SMEM_GEMM);
        smset = 1;
    }

    k_zero<<<(Nn + 255)/256, 256>>>();
    k_node_enc<<<(Nn + 3)/4, 256>>>(x, node_w, node_b);
    k_deg<<<(Ee + 255)/256, 256>>>(dst);
    k_scan1<<<SCB, 256>>>();
    k_scan2<<<1, 256>>>();
    k_scan3<<<SCB, 256>>>();
    k_sort<<<(Ee + 255)/256, 256>>>(src, dst);
    k_ea_enc<<<(Ee + 3)/4, 256>>>(eattr, edge_w, edge_b);
    k_ea_stat<<<Nn, 64>>>();
    k_amp<<<(Nn + 255)/256, 256>>>();

    for (int l = 0; l < NLAY; l++) {
        k_xagg<<<(Nn + 1)/2, 128>>>();
        k_prepB<<<192, 64>>>(conv_w, l);
        k_gemm_mma<<<MTILES, 256, SMEM_GEMM>>>(conv_b, l);
        k_bnzero<<<1, 128>>>();
        k_bnstat<<<128, 256>>>();
        k_bnapply<<<(Nn*64 + 255)/256, 256>>>(bn_g, bn_b, l);
    }

    k_pool<<<(Nn*64 + 255)/256, 256>>>(batch);
    k_final<<<1, 256>>>(f1w, f1b, f2w, f2b, f3w, f3b, out);
}

// round 15
// speedup vs baseline: 1.9321x; 1.1890x over previous
#include <cuda_runtime.h>
#include <cuda_fp16.h>
#include <math.h>
#include <stdint.h>

#define Nn 50000
#define Ee 800000
#define HID 64
#define EAD 16
#define NLAY 3
#define NCLS 10
#define NGR 64
#define KTOT 576
#define MTILES ((Nn + 127)/128)
#define SCB ((Nn + 255)/256)          // 196 scan blocks

// ---------------- static scratch ----------------
__device__ float d_x[(size_t)Nn*HID];
__device__ float d_ea[(size_t)Ee*HID];
__device__ int   d_srcs[Ee];
__device__ int   d_eperm[Ee];
__device__ int   d_degi[Nn];
__device__ int   d_off[Nn+1];
__device__ int   d_cursor[Nn];
__device__ int   d_bsum[SCB];
__device__ int   d_boff[SCB];
__device__ float d_amp[Nn], d_att[Nn];
__device__ float d_avglog;
__device__ __align__(16) __half d_aggA[(size_t)Nn*KTOT];
__device__ __align__(16) __half d_BH[(size_t)NLAY*192*KTOT];
__device__ __align__(16) __half d_BL[(size_t)NLAY*192*KTOT];
__device__ float d_cvec[NLAY*192];
__device__ float d_h[(size_t)Nn*HID];
__device__ float d_bnsum[NLAY*HID], d_bnss[NLAY*HID];
__device__ float d_pool[NGR*HID];
__device__ float d_cntg[NGR];

// ---------------- setup kernels ----------------
__global__ __launch_bounds__(256) void k_zero() {
    int i = blockIdx.x*blockDim.x + threadIdx.x;
    if (i < Nn) { d_degi[i] = 0; d_cursor[i] = 0; }
    if (i < NGR*HID) d_pool[i] = 0.f;
    if (i < NGR) d_cntg[i] = 0.f;
    if (i < NLAY*HID) { d_bnsum[i] = 0.f; d_bnss[i] = 0.f; }
    if (i == 0) { d_avglog = 0.f; d_off[Nn] = Ee; }
}

__global__ __launch_bounds__(256) void k_node_enc(const float* __restrict__ x,
                           const float* __restrict__ w, const float* __restrict__ b) {
    __shared__ float Ws[64*64];
    __shared__ float xs[4][64];
    int t = threadIdx.x;
    for (int i = t; i < 4096; i += 256) Ws[i] = w[i];
    int r = t >> 6, c = t & 63;
    int n = blockIdx.x*4 + r;
    if (n < Nn) xs[r][c] = x[(size_t)n*64 + c];
    __syncthreads();
    if (n < Nn) {
        float s = b[c];
        #pragma unroll
        for (int k = 0; k < 64; k++) s += xs[r][k]*Ws[k*64 + c];
        d_x[(size_t)n*64 + c] = s;
    }
}

__global__ __launch_bounds__(256) void k_deg(const int* __restrict__ dst) {
    int e = blockIdx.x*blockDim.x + threadIdx.x;
    if (e < Ee) atomicAdd(&d_degi[dst[e]], 1);
}

__global__ __launch_bounds__(256) void k_scan1() {
    __shared__ int si[256];
    __shared__ float sl[256];
    int t = threadIdx.x;
    int i = blockIdx.x*256 + t;
    int d = (i < Nn) ? d_degi[i] : 0;
    si[t] = d;
    sl[t] = (i < Nn) ? logf((float)d + 1.f) : 0.f;
    __syncthreads();
    for (int o = 128; o > 0; o >>= 1) {
        if (t < o) { si[t] += si[t+o]; sl[t] += sl[t+o]; }
        __syncthreads();
    }
    if (t == 0) {
        d_bsum[blockIdx.x] = si[0];
        atomicAdd(&d_avglog, sl[0]);
    }
}

__global__ __launch_bounds__(256) void k_scan2() {
    __shared__ int sm[256];
    int t = threadIdx.x;
    int v = (t < SCB) ? d_bsum[t] : 0;
    sm[t] = v; __syncthreads();
    for (int o = 1; o < 256; o <<= 1) {
        int u = (t >= o) ? sm[t-o] : 0;
        __syncthreads();
        sm[t] += u;
        __syncthreads();
    }
    if (t < SCB) d_boff[t] = sm[t] - v;
}

__global__ __launch_bounds__(256) void k_scan3() {
    __shared__ int sm[256];
    int t = threadIdx.x;
    int i = blockIdx.x*256 + t;
    int d = (i < Nn) ? d_degi[i] : 0;
    sm[t] = d; __syncthreads();
    for (int o = 1; o < 256; o <<= 1) {
        int u = (t >= o) ? sm[t-o] : 0;
        __syncthreads();
        sm[t] += u;
        __syncthreads();
    }
    if (i < Nn) d_off[i] = sm[t] - d + d_boff[blockIdx.x];
}

__global__ __launch_bounds__(256) void k_sort(const int* __restrict__ src,
                                              const int* __restrict__ dst) {
    int e = blockIdx.x*blockDim.x + threadIdx.x;
    if (e < Ee) {
        int d = dst[e];
        int r = atomicAdd(&d_cursor[d], 1);
        int pos = d_off[d] + r;
        d_srcs[pos]  = src[e];
        d_eperm[pos] = e;
    }
}

__global__ __launch_bounds__(256) void k_ea_enc(const float* __restrict__ ea,
                         const float* __restrict__ w, const float* __restrict__ b) {
    __shared__ float Ws[16*64];
    __shared__ float es[4][16];
    int t = threadIdx.x;
    for (int i = t; i < 1024; i += 256) Ws[i] = w[i];
    int r = t >> 6, c = t & 63;
    int p = blockIdx.x*4 + r;
    if (p < Ee && c < 16) {
        int e = d_eperm[p];
        es[r][c] = ea[(size_t)e*EAD + c];
    }
    __syncthreads();
    if (p < Ee) {
        float s = b[c];
        #pragma unroll
        for (int k = 0; k < 16; k++) s += es[r][k]*Ws[k*64 + c];
        d_ea[(size_t)p*64 + c] = s;
    }
}

// ONCE: ea-side segment stats (layer-invariant) -> ea columns of d_aggA
__global__ __launch_bounds__(64) void k_ea_stat() {
    int n = blockIdx.x;
    int c = threadIdx.x;
    int e0 = d_off[n], e1 = d_off[n+1];
    float s = 0.f, ss = 0.f, mx = -3.4e38f, mn = 3.4e38f;
    for (int p = e0; p < e1; p++) {
        float v = d_ea[(size_t)p*64 + c];
        s += v; ss += v*v;
        mx = fmaxf(mx, v); mn = fminf(mn, v);
    }
    int deg = e1 - e0;
    float inv = 1.f / fmaxf((float)deg, 1.f);
    float mean = s*inv;
    float sd   = sqrtf(fmaxf(ss*inv - mean*mean, 0.f) + 1e-5f);
    if (deg == 0) { mx = 0.f; mn = 0.f; }
    size_t b = (size_t)n*KTOT + 64 + c;
    d_aggA[b]       = __float2half(mean);
    d_aggA[b + 128] = __float2half(mn);
    d_aggA[b + 256] = __float2half(mx);
    d_aggA[b + 384] = __float2half(sd);
}

__global__ __launch_bounds__(256) void k_amp() {
    int n = blockIdx.x*blockDim.x + threadIdx.x;
    if (n < Nn) {
        float degc = fmaxf((float)d_degi[n], 1.f);
        float ld = logf(degc + 1.f);
        float avg = d_avglog / (float)Nn;
        d_amp[n] = ld/avg;
        d_att[n] = avg/ld;
    }
}

// ONCE: folded B for ALL layers [l][192 x 576] fp16 hi/lo + cvec
__global__ __launch_bounds__(64) void k_prepB(const float* __restrict__ convw) {
    int bid = blockIdx.x;           // 0..575
    int l = bid / 192, c = bid % 192;
    int tch = c >> 6, cc = c & 63;
    const float* W = convw + ((size_t)l*2304 + (size_t)tch*768)*64;
    const int LUT[8] = {64,128,256,320,448,512,640,704};
    size_t base = ((size_t)l*192 + c)*KTOT;
    for (int k = threadIdx.x; k < KTOT; k += 64) {
        float v;
        if (k < 512) {
            v = W[(size_t)(LUT[k >> 6] + (k & 63))*64 + cc];
        } else {
            int r = k - 512;
            v = W[(size_t)r*64 + cc] + W[(size_t)(192 + r)*64 + cc] + W[(size_t)(384 + r)*64 + cc];
        }
        __half h = __float2half(v);
        d_BH[base + k] = h;
        d_BL[base + k] = __float2half(v - __half2float(h));
    }
    if (threadIdx.x == 0) {
        float s = 0.f;
        for (int r = 0; r < 64; r++) s += W[(size_t)(576 + r)*64 + cc];
        d_cvec[l*192 + c] = 0.0031622776601683794f * s;
    }
}

// ---------------- per-layer kernels ----------------
// x-src side stats + masked x (2 nodes/block, 128 threads)
__global__ __launch_bounds__(128) void k_xagg() {
    int t = threadIdx.x;
    int sub = t >> 6, c = t & 63;
    int n = blockIdx.x*2 + sub;
    if (n >= Nn) return;
    int e0 = d_off[n], e1 = d_off[n+1];
    float s = 0.f, ss = 0.f, mx = -3.4e38f, mn = 3.4e38f;
    for (int p = e0; p < e1; p++) {
        float v = d_x[(size_t)d_srcs[p]*64 + c];
        s += v; ss += v*v;
        mx = fmaxf(mx, v); mn = fminf(mn, v);
    }
    int deg = e1 - e0;
    float inv = 1.f / fmaxf((float)deg, 1.f);
    float mean = s*inv;
    float sd   = sqrtf(fmaxf(ss*inv - mean*mean, 0.f) + 1e-5f);
    if (deg == 0) { mx = 0.f; mn = 0.f; }
    size_t b = (size_t)n*KTOT + c;
    d_aggA[b]       = __float2half(mean);
    d_aggA[b + 128] = __float2half(mn);
    d_aggA[b + 256] = __float2half(mx);
    d_aggA[b + 384] = __float2half(sd);
    float m2 = (deg > 0) ? d_x[(size_t)n*64 + c] : 0.f;
    d_aggA[(size_t)n*KTOT + 512 + c] = __float2half(m2);
}

// --- combo-inner fp16 GEMM + fused combine + BN-stat epilogue ---
#define ASTR 40
#define SMA_HALVES (128*ASTR)                  // 5120
#define SMB_HALVES (192*ASTR)                  // 7680
#define BUF_HALVES (SMA_HALVES + 2*SMB_HALVES) // 20480
#define SMEM_GEMM (2*BUF_HALVES*2)             // 81920 bytes
#define YSTR 196

__global__ __launch_bounds__(256) void k_gemm_mma(const float* __restrict__ convb, int l) {
    extern __shared__ __half smg[];
    int t = threadIdx.x;
    int lane = t & 31, warp = t >> 5;
    int warpM = warp & 3, warpN = warp >> 2;     // 4 x 2 warp grid
    int bm = blockIdx.x * 128;
    int g = lane >> 2, tg = lane & 3;

    const __half* BHl = d_BH + (size_t)l*192*KTOT;
    const __half* BLl = d_BL + (size_t)l*192*KTOT;

    float c[2][12][4];
    #pragma unroll
    for (int m = 0; m < 2; m++)
        #pragma unroll
        for (int j = 0; j < 12; j++)
            #pragma unroll
            for (int q = 0; q < 4; q++) c[m][j][q] = 0.f;

    int arow = t >> 1, akoff = (t & 1) * 16;
    uint4 ra0, ra1, rh0, rh1, rh2, rl0, rl1, rl2;

    const int NIT = 18;                          // 18 chunks, both combos per chunk
    {
        int grow = bm + arow;
        if (grow < Nn) {
            const __half* p = d_aggA + (size_t)grow*KTOT + akoff;
            ra0 = *(const uint4*)p; ra1 = *(const uint4*)(p + 8);
        } else { ra0 = make_uint4(0,0,0,0); ra1 = ra0; }
        int u0 = t, u1 = t + 256, u2 = t + 512;
        rh0 = *(const uint4*)(BHl + (size_t)(u0>>2)*KTOT + (u0&3)*8);
        rh1 = *(const uint4*)(BHl + (size_t)(u1>>2)*KTOT + (u1&3)*8);
        rh2 = *(const uint4*)(BHl + (size_t)(u2>>2)*KTOT + (u2&3)*8);
        rl0 = *(const uint4*)(BLl + (size_t)(u0>>2)*KTOT + (u0&3)*8);
        rl1 = *(const uint4*)(BLl + (size_t)(u1>>2)*KTOT + (u1&3)*8);
        rl2 = *(const uint4*)(BLl + (size_t)(u2>>2)*KTOT + (u2&3)*8);
    }

    for (int it = 0; it < NIT; it++) {
        __half* buf   = smg + (it & 1)*BUF_HALVES;
        __half* abuf  = buf;
        __half* bhbuf = buf + SMA_HALVES;
        __half* blbuf = buf + SMA_HALVES + SMB_HALVES;
        *(uint4*)(abuf + arow*ASTR + akoff)     = ra0;
        *(uint4*)(abuf + arow*ASTR + akoff + 8) = ra1;
        {
            int u0 = t, u1 = t + 256, u2 = t + 512;
            *(uint4*)(bhbuf + (u0>>2)*ASTR + (u0&3)*8) = rh0;
            *(uint4*)(bhbuf + (u1>>2)*ASTR + (u1&3)*8) = rh1;
            *(uint4*)(bhbuf + (u2>>2)*ASTR + (u2&3)*8) = rh2;
            *(uint4*)(blbuf + (u0>>2)*ASTR + (u0&3)*8) = rl0;
            *(uint4*)(blbuf + (u1>>2)*ASTR + (u1&3)*8) = rl1;
            *(uint4*)(blbuf + (u2>>2)*ASTR + (u2&3)*8) = rl2;
        }
        __syncthreads();
        if (it + 1 < NIT) {
            int k0 = (it + 1) * 32;
            int grow = bm + arow;
            if (grow < Nn) {
                const __half* p = d_aggA + (size_t)grow*KTOT + k0 + akoff;
                ra0 = *(const uint4*)p; ra1 = *(const uint4*)(p + 8);
            } else { ra0 = make_uint4(0,0,0,0); ra1 = ra0; }
            int u0 = t, u1 = t + 256, u2 = t + 512;
            rh0 = *(const uint4*)(BHl + (size_t)(u0>>2)*KTOT + k0 + (u0&3)*8);
            rh1 = *(const uint4*)(BHl + (size_t)(u1>>2)*KTOT + k0 + (u1&3)*8);
            rh2 = *(const uint4*)(BHl + (size_t)(u2>>2)*KTOT + k0 + (u2&3)*8);
            rl0 = *(const uint4*)(BLl + (size_t)(u0>>2)*KTOT + k0 + (u0&3)*8);
            rl1 = *(const uint4*)(BLl + (size_t)(u1>>2)*KTOT + k0 + (u1&3)*8);
            rl2 = *(const uint4*)(BLl + (size_t)(u2>>2)*KTOT + k0 + (u2&3)*8);
        }
        #pragma unroll
        for (int ks = 0; ks < 2; ks++) {
            uint32_t a[2][4];
            #pragma unroll
            for (int m = 0; m < 2; m++) {
                int r0 = warpM*32 + m*16;
                const __half* p0 = abuf + (r0 + g)*ASTR + ks*16 + tg*2;
                const __half* p1 = abuf + (r0 + g + 8)*ASTR + ks*16 + tg*2;
                a[m][0] = *(const uint32_t*)p0;
                a[m][1] = *(const uint32_t*)p1;
                a[m][2] = *(const uint32_t*)(p0 + 8);
                a[m][3] = *(const uint32_t*)(p1 + 8);
            }
            #pragma unroll
            for (int cb = 0; cb < 2; cb++) {
                const __half* bb = cb ? blbuf : bhbuf;
                #pragma unroll
                for (int j = 0; j < 12; j++) {
                    int n0 = warpN*96 + j*8 + g;
                    const __half* pb = bb + n0*ASTR + ks*16 + tg*2;
                    uint32_t b0 = *(const uint32_t*)pb;
                    uint32_t b1 = *(const uint32_t*)(pb + 8);
                    #pragma unroll
                    for (int m = 0; m < 2; m++) {
                        asm volatile(
                            "mma.sync.aligned.m16n8k16.row.col.f32.f16.f16.f32 "
                            "{%0,%1,%2,%3}, {%4,%5,%6,%7}, {%8,%9}, {%0,%1,%2,%3};"
                            : "+f"(c[m][j][0]), "+f"(c[m][j][1]),
                              "+f"(c[m][j][2]), "+f"(c[m][j][3])
                            : "r"(a[m][0]), "r"(a[m][1]), "r"(a[m][2]), "r"(a[m][3]),
                              "r"(b0), "r"(b1));
                    }
                }
            }
        }
        __syncthreads();
    }

    // fused epilogue: combine + write d_h + BN partial stats
    float* ysm = (float*)smg;
    int ecol = t & 63;
    int erow0 = t >> 6;
    float cv0 = d_cvec[l*192 + ecol];
    float cv1 = d_cvec[l*192 + 64 + ecol];
    float cv2 = d_cvec[l*192 + 128 + ecol];
    float bias = convb[l*64 + ecol];
    float bs = 0.f, bss = 0.f;
    #pragma unroll
    for (int half = 0; half < 2; half++) {
        if (half) __syncthreads();
        if ((warpM >> 1) == half) {
            int lr = (warpM & 1)*32;
            #pragma unroll
            for (int m = 0; m < 2; m++) {
                int lrow = lr + m*16 + g;
                #pragma unroll
                for (int j = 0; j < 12; j++) {
                    int col = warpN*96 + j*8 + tg*2;
                    ysm[lrow*YSTR + col]         = c[m][j][0];
                    ysm[lrow*YSTR + col + 1]     = c[m][j][1];
                    ysm[(lrow+8)*YSTR + col]     = c[m][j][2];
                    ysm[(lrow+8)*YSTR + col + 1] = c[m][j][3];
                }
            }
        }
        __syncthreads();
        #pragma unroll
        for (int q = 0; q < 16; q++) {
            int row = erow0 + q*4;
            int n = bm + half*64 + row;
            if (n < Nn) {
                float y0 = ysm[row*YSTR + ecol]       + cv0;
                float y1 = ysm[row*YSTR + 64 + ecol]  + cv1;
                float y2 = ysm[row*YSTR + 128 + ecol] + cv2;
                float h = y0 + d_amp[n]*y1 + d_att[n]*y2 + bias;
                d_h[(size_t)n*64 + ecol] = h;
                bs += h; bss += h*h;
            }
        }
    }
    __syncthreads();
    ysm[t] = bs; ysm[256 + t] = bss;
    __syncthreads();
    if (t < 64) {
        float a = ysm[t] + ysm[t+64] + ysm[t+128] + ysm[t+192];
        float b2 = ysm[256+t] + ysm[256+t+64] + ysm[256+t+128] + ysm[256+t+192];
        atomicAdd(&d_bnsum[l*64 + t], a);
        atomicAdd(&d_bnss[l*64 + t], b2);
    }
}

__global__ __launch_bounds__(256) void k_bnapply(const float* __restrict__ g,
                                                 const float* __restrict__ b, int l) {
    int i = blockIdx.x*blockDim.x + threadIdx.x;
    if (i >= Nn*64) return;
    int j = i & 63;
    float mu  = d_bnsum[l*64 + j] / (float)Nn;
    float var = d_bnss[l*64 + j] / (float)Nn - mu*mu;
    float h = (d_h[i] - mu) * rsqrtf(var + 1e-5f) * g[l*64 + j] + b[l*64 + j];
    d_x[i] = fmaxf(h, 0.f) + d_x[i];
}

// last layer: bnapply + global mean pool accumulation fused
__global__ __launch_bounds__(256) void k_bnapply_pool(const float* __restrict__ g,
                        const float* __restrict__ b, int l,
                        const int* __restrict__ batch) {
    int i = blockIdx.x*blockDim.x + threadIdx.x;
    if (i >= Nn*64) return;
    int n = i >> 6, j = i & 63;
    float mu  = d_bnsum[l*64 + j] / (float)Nn;
    float var = d_bnss[l*64 + j] / (float)Nn - mu*mu;
    float h = (d_h[i] - mu) * rsqrtf(var + 1e-5f) * g[l*64 + j] + b[l*64 + j];
    float v = fmaxf(h, 0.f) + d_x[i];
    d_x[i] = v;
    int bg = batch[n];
    atomicAdd(&d_pool[bg*64 + j], v);
    if (j == 0) atomicAdd(&d_cntg[bg], 1.f);
}

// ---------------- readout ----------------
__global__ __launch_bounds__(256) void k_final(const float* __restrict__ f1w,
                        const float* __restrict__ f1b,
                        const float* __restrict__ f2w, const float* __restrict__ f2b,
                        const float* __restrict__ f3w, const float* __restrict__ f3b,
                        float* __restrict__ out) {
    __shared__ float G[64*64], H1[64*32], H2[64*16];
    int t = threadIdx.x;
    for (int i = t; i < 4096; i += 256) {
        int g = i >> 6;
        G[i] = d_pool[i] / fmaxf(d_cntg[g], 1.f);
    }
    __syncthreads();
    for (int i = t; i < 2048; i += 256) {
        int g = i >> 5, o = i & 31;
        float s = f1b[o];
        #pragma unroll
        for (int k = 0; k < 64; k++) s += G[g*64 + k]*f1w[k*32 + o];
        H1[i] = fmaxf(s, 0.f);
    }
    __syncthreads();
    for (int i = t; i < 1024; i += 256) {
        int g = i >> 4, o = i & 15;
        float s = f2b[o];
        #pragma unroll
        for (int k = 0; k < 32; k++) s += H1[g*32 + k]*f2w[k*16 + o];
        H2[i] = fmaxf(s, 0.f);
    }
    __syncthreads();
    for (int i = t; i < 640; i += 256) {
        int g = i/10, o = i%10;
        float s = f3b[o];
        #pragma unroll
        for (int k = 0; k < 16; k++) s += H2[g*16 + k]*f3w[k*10 + o];
        out[i] = s;
    }
}

// ---------------- launch ----------------
extern "C" void kernel_launch(void* const* d_in, const int* in_sizes, int n_in,
                              void* d_out, int out_size) {
    const float* x      = (const float*)d_in[0];
    const int*   ei     = (const int*)  d_in[1];
    const int*   batch  = (const int*)  d_in[2];
    const float* eattr  = (const float*)d_in[3];
    const float* node_w = (const float*)d_in[4];
    const float* node_b = (const float*)d_in[5];
    const float* edge_w = (const float*)d_in[6];
    const float* edge_b = (const float*)d_in[7];
    const float* conv_w = (const float*)d_in[8];
    const float* conv_b = (const float*)d_in[9];
    const float* bn_g   = (const float*)d_in[10];
    const float* bn_b   = (const float*)d_in[11];
    const float* f1w    = (const float*)d_in[12];
    const float* f1b    = (const float*)d_in[13];
    const float* f2w    = (const float*)d_in[14];
    const float* f2b    = (const float*)d_in[15];
    const float* f3w    = (const float*)d_in[16];
    const float* f3b    = (const float*)d_in[17];
    float* out = (float*)d_out;

    const int* src = ei;
    const int* dst = ei + Ee;

    static int smset = 0;
    if (!smset) {
        cudaFuncSetAttribute(k_gemm_mma, cudaFuncAttributeMaxDynamicSharedMemorySize, SMEM_GEMM);
        smset = 1;
    }

    k_zero<<<(Nn + 255)/256, 256>>>();
    k_node_enc<<<(Nn + 3)/4, 256>>>(x, node_w, node_b);
    k_deg<<<(Ee + 255)/256, 256>>>(dst);
    k_scan1<<<SCB, 256>>>();
    k_scan2<<<1, 256>>>();
    k_scan3<<<SCB, 256>>>();
    k_sort<<<(Ee + 255)/256, 256>>>(src, dst);
    k_ea_enc<<<(Ee + 3)/4, 256>>>(eattr, edge_w, edge_b);
    k_ea_stat<<<Nn, 64>>>();
    k_amp<<<(Nn + 255)/256, 256>>>();
    k_prepB<<<NLAY*192, 64>>>(conv_w);

    for (int l = 0; l < NLAY; l++) {
        k_xagg<<<(Nn + 1)/2, 128>>>();
        k_gemm_mma<<<MTILES, 256, SMEM_GEMM>>>(conv_b, l);
        if (l < NLAY - 1)
            k_bnapply<<<(Nn*64 + 255)/256, 256>>>(bn_g, bn_b, l);
        else
            k_bnapply_pool<<<(Nn*64 + 255)/256, 256>>>(bn_g, bn_b, l, batch);
    }

    k_final<<<1, 256>>>(f1w, f1b, f2w, f2b, f3w, f3b, out);
}